// round 8
// baseline (speedup 1.0000x reference)
#include <cuda_runtime.h>
#include <cuda_bf16.h>
#include <math.h>
#include <float.h>
#include <stdint.h>

#define N_NODES 50000
#define N_EDGES 600000
#define N_GRAPHS 512
#define HID 128
#define LAT 64
#define NL 4
#define NSLOT 10

// ======================= scratch =======================
__device__ float g_t[N_NODES * HID];
__device__ float g_hs[NL][N_NODES * HID];
__device__ int   g_deg[N_NODES];
__device__ int   g_ptr[N_NODES + 1];
__device__ int   g_cursor[N_NODES];
__device__ int   g_srclist[N_EDGES];
__device__ int   g_bsum[64];
__device__ float g_sum[NSLOT * HID];
__device__ float g_sumsq[NSLOT * HID];
__device__ float g_psum[N_GRAPHS * HID];
__device__ float g_pmax[N_GRAPHS * HID];
__device__ int   g_pcnt[N_GRAPHS];
// per weight: 32KB hi + 32KB lo, B^T layout [n][k] row-major bf16
__device__ unsigned char g_wsplit[8][65536];

__device__ __forceinline__ float gelu_exact(float x) {
    return 0.5f * x * (1.0f + erff(x * 0.70710678118654752f));
}
__device__ __forceinline__ void atomicMaxF(float* addr, float v) {
    if (__float_as_int(v) >= 0) atomicMax((int*)addr, __float_as_int(v));
    else atomicMin((unsigned int*)addr, __float_as_uint(v));
}
__device__ __forceinline__ uint32_t smem_u32(const void* p) {
    uint32_t a;
    asm("{ .reg .u64 t; cvta.to.shared.u64 t, %1; cvt.u32.u64 %0, t; }" : "=r"(a) : "l"(p));
    return a;
}

#define LDMATRIX_X4(r, addr) \
    asm volatile("ldmatrix.sync.aligned.m8n8.x4.shared.b16 {%0,%1,%2,%3}, [%4];" \
        : "=r"((r)[0]), "=r"((r)[1]), "=r"((r)[2]), "=r"((r)[3]) : "r"(addr))

#define MMA16816(c, a, b) \
    asm volatile("mma.sync.aligned.m16n8k16.row.col.f32.bf16.bf16.f32 " \
        "{%0,%1,%2,%3}, {%4,%5,%6,%7}, {%8,%9}, {%0,%1,%2,%3};" \
        : "+f"((c)[0]), "+f"((c)[1]), "+f"((c)[2]), "+f"((c)[3]) \
        : "r"((a)[0]), "r"((a)[1]), "r"((a)[2]), "r"((a)[3]), "r"((b)[0]), "r"((b)[1]))

// finalize BN stats for `slot` into smem scale/shift (first 128 threads)
__device__ __forceinline__ void finalize_to_smem(int slot, const float* gamma,
                                                 const float* beta,
                                                 float* sScale, float* sShift, int tid) {
    if (tid < HID) {
        const float invN = 1.0f / N_NODES;
        float mean = g_sum[slot * HID + tid] * invN;
        float var  = g_sumsq[slot * HID + tid] * invN - mean * mean;
        float sc = __ldg(&gamma[tid]) * rsqrtf(var + 1e-5f);
        sScale[tid] = sc;
        sShift[tid] = __ldg(&beta[tid]) - mean * sc;
    }
}

// ======================= init (covers pooling buffers too!) =======================
__global__ void zero_init_kernel() {
    int i = blockIdx.x * blockDim.x + threadIdx.x;
    if (i < NSLOT * HID) { g_sum[i] = 0.f; g_sumsq[i] = 0.f; }
    if (i < N_NODES) g_deg[i] = 0;
    if (i < N_GRAPHS * HID) { g_psum[i] = 0.f; g_pmax[i] = -FLT_MAX; }
    if (i < N_GRAPHS) g_pcnt[i] = 0;
}

__global__ void colstats_kernel(const float* __restrict__ A, int M, int slot) {
    int c = threadIdx.x;
    float s = 0.f, s2 = 0.f;
    for (int n = blockIdx.x; n < M; n += gridDim.x) {
        float v = A[n * HID + c];
        s += v; s2 += v * v;
    }
    atomicAdd(&g_sum[slot * HID + c], s);
    atomicAdd(&g_sumsq[slot * HID + c], s2);
}

// BN+GELU apply with inlined finalize (writes hidden state for jk)
__global__ void bn_apply_kernel(const float* __restrict__ in, float* __restrict__ out,
                                int slot, const float* __restrict__ gamma,
                                const float* __restrict__ beta) {
    __shared__ float sScale[HID], sShift[HID];
    int tid = threadIdx.x;
    finalize_to_smem(slot, gamma, beta, sScale, sShift, tid);
    __syncthreads();
    int idx = blockIdx.x * blockDim.x + tid;
    int c4 = idx & 31;
    float4 v  = ((const float4*)in)[idx];
    float4 sc = ((const float4*)sScale)[c4];
    float4 sh = ((const float4*)sShift)[c4];
    v.x = gelu_exact(v.x * sc.x + sh.x);
    v.y = gelu_exact(v.y * sc.y + sh.y);
    v.z = gelu_exact(v.z * sc.z + sh.z);
    v.w = gelu_exact(v.w * sc.w + sh.w);
    ((float4*)out)[idx] = v;
}

// ---------------- CSR build ----------------
__global__ void hist_kernel(const int* __restrict__ dst) {
    int i = blockIdx.x * blockDim.x + threadIdx.x;
    if (i < N_EDGES) atomicAdd(&g_deg[dst[i]], 1);
}

__global__ void scan1_kernel() {     // per-block inclusive scan of degrees
    __shared__ int s[1024];
    int tid = threadIdx.x;
    int i = blockIdx.x * 1024 + tid;
    int v = (i < N_NODES) ? g_deg[i] : 0;
    s[tid] = v;
    __syncthreads();
#pragma unroll
    for (int d = 1; d < 1024; d <<= 1) {
        int t = (tid >= d) ? s[tid - d] : 0;
        __syncthreads();
        s[tid] += t;
        __syncthreads();
    }
    if (i < N_NODES) g_cursor[i] = s[tid];          // inclusive within block
    if (tid == 1023) g_bsum[blockIdx.x] = s[tid];
}

__global__ void scan3_kernel() {     // finalize ptr+cursor (block offset computed locally)
    __shared__ int boff;
    if (threadIdx.x == 0) {
        int s = 0;
        for (int k = 0; k < blockIdx.x; k++) s += g_bsum[k];
        boff = s;
    }
    __syncthreads();
    int i = blockIdx.x * 1024 + threadIdx.x;
    if (i < N_NODES) {
        int p = boff + g_cursor[i] - g_deg[i];
        g_ptr[i] = p;
        g_cursor[i] = p;
    }
    if (i == 0) g_ptr[N_NODES] = N_EDGES;
}

__global__ void scatter_kernel(const int* __restrict__ src, const int* __restrict__ dst) {
    int i = blockIdx.x * blockDim.x + threadIdx.x;
    if (i < N_EDGES) {
        int pos = atomicAdd(&g_cursor[dst[i]], 1);
        g_srclist[pos] = src[i];
    }
}

// ---------------- weight split prep: B^T[n][k] hi/lo bf16 ----------------
__global__ void wsplit_kernel(const float* __restrict__ fc1_w, const float* __restrict__ fc2_w) {
    int w = blockIdx.x >> 3;
    int l = w >> 1, which = w & 1;
    const float* W = (which ? fc2_w : fc1_w) + l * HID * HID;
    __nv_bfloat16* bh = (__nv_bfloat16*)(g_wsplit[w]);
    __nv_bfloat16* bl = (__nv_bfloat16*)(g_wsplit[w] + 32768);
    int chunk = blockIdx.x & 7;
    for (int i = threadIdx.x + chunk * 2048; i < (chunk + 1) * 2048; i += 256) {
        int n = i >> 7, k = i & 127;
        float v = W[k * HID + n];
        __nv_bfloat16 hi = __float2bfloat16_rn(v);
        bh[n * 128 + k] = hi;
        bl[n * 128 + k] = __float2bfloat16_rn(v - __bfloat162float(hi));
    }
}

// ---------------- HMMA GEMM 64x128 tile, 2 CTAs/SM ----------------
// MODE 1: A-load applies BN+GELU from `slot` (GEMM2)
// MODE 2: A-load gathers CSR neighbors: (1+eps)*self + sum (layers 1..3 GEMM1)
// MODE 3: MODE 2 + input-BN affine folded in: sc*G + (1+eps+deg)*sh (layer 0 GEMM1)
#define APAD 136
#define AT_BYTES (64 * APAD * 2)         // 17408
#define BT_BYTES (128 * APAD * 2)        // 34816
#define SM_AH 0
#define SM_AL AT_BYTES
#define SM_BH (2 * AT_BYTES)
#define SM_BL (2 * AT_BYTES + BT_BYTES)
#define SM_SC (2 * AT_BYTES + 2 * BT_BYTES)   // 104448
#define SM_SH (SM_SC + 512)
#define TC_SMEM (SM_SC + 1024)               // 105472 -> 2 CTAs/SM

template <int MODE>
__global__ void __launch_bounds__(256, 2)
mma_gemm_kernel(const float* __restrict__ A, int widx, const float* __restrict__ bias,
                float* __restrict__ C, int M, int slot,
                const float* __restrict__ gamma, const float* __restrict__ beta,
                int oslot, const float* __restrict__ eps_p, int layer) {
    extern __shared__ unsigned char smem[];
    int tid = threadIdx.x, lane = tid & 31, wid = tid >> 5;
    int m0 = blockIdx.x * 64;
    uint32_t sb = smem_u32(smem);
    float* sScale = (float*)(smem + SM_SC);
    float* sShift = (float*)(smem + SM_SH);

    if (MODE == 1 || MODE == 3) {
        finalize_to_smem(slot, gamma, beta, sScale, sShift, tid);
        __syncthreads();
    }

    // ---- B: copy pre-split B^T (hi+lo) with row padding ----
    {
        const uint4* srcH = (const uint4*)(g_wsplit[widx]);
        const uint4* srcL = (const uint4*)(g_wsplit[widx] + 32768);
#pragma unroll
        for (int it = 0; it < 8; it++) {
            int i = tid + it * 256;
            int n = i >> 4, s = i & 15;
            *(uint4*)(smem + SM_BH + n * (APAD * 2) + s * 16) = __ldg(srcH + i);
            *(uint4*)(smem + SM_BL + n * (APAD * 2) + s * 16) = __ldg(srcL + i);
        }
    }

    // ---- A: build tile (4 threads/row, 32 cols each), split hi/lo ----
    {
        int r = tid >> 2, qt = tid & 3;
        int n = m0 + r;
        float4 acc[8];
        float shf = 0.f;

        if (MODE >= 2) {
            // fused GIN aggregation: (1+eps)*self + sum of neighbors
            if (n < M) {
                float ev = __ldg(&eps_p[layer]);
                float op = 1.0f + ev;
                const float4* self = (const float4*)(A + (size_t)n * HID) + qt * 8;
#pragma unroll
                for (int k = 0; k < 8; k++) {
                    float4 t = __ldg(self + k);
                    acc[k] = make_float4(op * t.x, op * t.y, op * t.z, op * t.w);
                }
                int b = g_ptr[n], e = g_ptr[n + 1];
                for (int j = b; j < e; j++) {
                    int sidx = __ldg(&g_srclist[j]);
                    const float4* nb = (const float4*)(A + (size_t)sidx * HID) + qt * 8;
#pragma unroll
                    for (int k = 0; k < 8; k++) {
                        float4 t = __ldg(nb + k);
                        acc[k].x += t.x; acc[k].y += t.y;
                        acc[k].z += t.z; acc[k].w += t.w;
                    }
                }
                shf = op + (float)(e - b);   // (1+eps) + deg for affine fold
            } else {
#pragma unroll
                for (int k = 0; k < 8; k++) acc[k] = make_float4(0.f, 0.f, 0.f, 0.f);
            }
        } else {
            bool valid = n < M;
            const float4* Arow = (const float4*)(A + (size_t)n * HID) + qt * 8;
#pragma unroll
            for (int k = 0; k < 8; k++)
                acc[k] = valid ? __ldg(Arow + k) : make_float4(0.f, 0.f, 0.f, 0.f);
        }

#pragma unroll
        for (int k = 0; k < 8; k++) {
            int col = qt * 32 + k * 4;
            float4 v = acc[k];
            if (MODE == 1) {
                float4 sc = ((const float4*)sScale)[col >> 2];
                float4 sh = ((const float4*)sShift)[col >> 2];
                v.x = gelu_exact(v.x * sc.x + sh.x);
                v.y = gelu_exact(v.y * sc.y + sh.y);
                v.z = gelu_exact(v.z * sc.z + sh.z);
                v.w = gelu_exact(v.w * sc.w + sh.w);
            } else if (MODE == 3) {
                float4 sc = ((const float4*)sScale)[col >> 2];
                float4 sh = ((const float4*)sShift)[col >> 2];
                v.x = v.x * sc.x + shf * sh.x;
                v.y = v.y * sc.y + shf * sh.y;
                v.z = v.z * sc.z + shf * sh.z;
                v.w = v.w * sc.w + shf * sh.w;
            }
            __nv_bfloat16 h0 = __float2bfloat16_rn(v.x), h1 = __float2bfloat16_rn(v.y);
            __nv_bfloat16 h2 = __float2bfloat16_rn(v.z), h3 = __float2bfloat16_rn(v.w);
            float l0 = v.x - __bfloat162float(h0), l1 = v.y - __bfloat162float(h1);
            float l2 = v.z - __bfloat162float(h2), l3 = v.w - __bfloat162float(h3);
            uint2 hp, lp;
            hp.x = (uint32_t)__bfloat16_as_ushort(h0) | ((uint32_t)__bfloat16_as_ushort(h1) << 16);
            hp.y = (uint32_t)__bfloat16_as_ushort(h2) | ((uint32_t)__bfloat16_as_ushort(h3) << 16);
            lp.x = (uint32_t)__bfloat16_as_ushort(__float2bfloat16_rn(l0)) |
                   ((uint32_t)__bfloat16_as_ushort(__float2bfloat16_rn(l1)) << 16);
            lp.y = (uint32_t)__bfloat16_as_ushort(__float2bfloat16_rn(l2)) |
                   ((uint32_t)__bfloat16_as_ushort(__float2bfloat16_rn(l3)) << 16);
            uint32_t off = r * (APAD * 2) + col * 2;
            *(uint2*)(smem + SM_AH + off) = hp;
            *(uint2*)(smem + SM_AL + off) = lp;
        }
    }
    __syncthreads();

    // ---- MMA mainloop: warp grid 2(M) x 4(N), warp tile 32x32 ----
    int wm = wid & 1, wn = wid >> 1;
    int mbase = wm * 32, nbase = wn * 32;
    float acc[2][4][4];
#pragma unroll
    for (int i = 0; i < 2; i++)
#pragma unroll
        for (int j = 0; j < 4; j++)
#pragma unroll
            for (int c = 0; c < 4; c++) acc[i][j][c] = 0.f;

    int q = lane >> 3, riq = lane & 7;
#pragma unroll
    for (int ks = 0; ks < 8; ks++) {
        uint32_t ah[2][4], al[2][4], bh[4][2], bl[4][2];
#pragma unroll
        for (int i = 0; i < 2; i++) {
            int row = mbase + i * 16 + (q & 1) * 8 + riq;
            int kb = ks * 16 + (q >> 1) * 8;
            uint32_t addr = sb + SM_AH + row * (APAD * 2) + kb * 2;
            LDMATRIX_X4(ah[i], addr);
            LDMATRIX_X4(al[i], addr + AT_BYTES);
        }
#pragma unroll
        for (int j = 0; j < 2; j++) {
            int n = nbase + j * 16 + (q >> 1) * 8 + riq;
            int kb = ks * 16 + (q & 1) * 8;
            uint32_t addr = sb + SM_BH + n * (APAD * 2) + kb * 2;
            uint32_t t4[4];
            LDMATRIX_X4(t4, addr);
            bh[j * 2][0] = t4[0]; bh[j * 2][1] = t4[1];
            bh[j * 2 + 1][0] = t4[2]; bh[j * 2 + 1][1] = t4[3];
            LDMATRIX_X4(t4, addr + BT_BYTES);
            bl[j * 2][0] = t4[0]; bl[j * 2][1] = t4[1];
            bl[j * 2 + 1][0] = t4[2]; bl[j * 2 + 1][1] = t4[3];
        }
#pragma unroll
        for (int i = 0; i < 2; i++)
#pragma unroll
            for (int j = 0; j < 4; j++) {
                MMA16816(acc[i][j], ah[i], bh[j]);
                MMA16816(acc[i][j], ah[i], bl[j]);
                MMA16816(acc[i][j], al[i], bh[j]);
            }
    }
    __syncthreads();   // tiles consumed; reuse smem for C staging

    // ---- epilogue: regs -> smem (+bias) -> coalesced STG + fused stats ----
    float* sC = (float*)smem;   // 64 x 132 floats (fits in Ah+Al region)
    int g = lane >> 2, tc = (lane & 3) * 2;
#pragma unroll
    for (int i = 0; i < 2; i++) {
        int row0 = mbase + i * 16 + g;
#pragma unroll
        for (int j = 0; j < 4; j++) {
            int col = nbase + j * 8 + tc;
            float b0 = __ldg(&bias[col]), b1 = __ldg(&bias[col + 1]);
            sC[row0 * 132 + col]           = acc[i][j][0] + b0;
            sC[row0 * 132 + col + 1]       = acc[i][j][1] + b1;
            sC[(row0 + 8) * 132 + col]     = acc[i][j][2] + b0;
            sC[(row0 + 8) * 132 + col + 1] = acc[i][j][3] + b1;
        }
    }
    __syncthreads();

    {
        int r2 = tid >> 2, qt = tid & 3;
        if (m0 + r2 < M) {
            float4* dst = (float4*)(C + (size_t)(m0 + r2) * HID + qt * 32);
            const float4* src = (const float4*)(sC + r2 * 132 + qt * 32);
#pragma unroll
            for (int i = 0; i < 8; i++) dst[i] = src[i];
        }
    }

    {
        int nrows = min(64, M - m0);
        int c = tid & 127;
        int rbeg = (tid >> 7) * 32;
        int rend = min(rbeg + 32, nrows);
        float s = 0.f, s2 = 0.f;
        for (int rr = rbeg; rr < rend; rr++) {
            float v = sC[rr * 132 + c];
            s += v; s2 += v * v;
        }
        atomicAdd(&g_sum[oslot * HID + c], s);
        atomicAdd(&g_sumsq[oslot * HID + c], s2);
    }
}

// ---------------- fused JK attention + pooling (warp-autonomous) ----------------
#define JKP_BLOCKS 500
#define JKP_WARPS (JKP_BLOCKS * 8)
__global__ void jk_pool_kernel(const int* __restrict__ batch, const float* __restrict__ att) {
    int wgid = blockIdx.x * 8 + (threadIdx.x >> 5);
    int lane = threadIdx.x & 31;
    const int CH = (N_NODES + JKP_WARPS - 1) / JKP_WARPS;   // 13
    int n0 = wgid * CH, n1 = min(n0 + CH, N_NODES);
    if (n0 >= n1) return;
    int c0 = lane * 4;

    float4 attc[NL];
#pragma unroll
    for (int l = 0; l < NL; l++)
        attc[l] = __ldg((const float4*)(att + l * HID) + lane);

    int g = __ldg(&batch[n0]);
    float4 s4 = make_float4(0.f, 0.f, 0.f, 0.f);
    float4 m4 = make_float4(-FLT_MAX, -FLT_MAX, -FLT_MAX, -FLT_MAX);
    int cnt = 0;

    for (int n = n0; n < n1; n++) {
        int gn = __ldg(&batch[n]);
        if (gn != g) {
            if (cnt > 0) {
                atomicAdd(&g_psum[g * HID + c0], s4.x);
                atomicAdd(&g_psum[g * HID + c0 + 1], s4.y);
                atomicAdd(&g_psum[g * HID + c0 + 2], s4.z);
                atomicAdd(&g_psum[g * HID + c0 + 3], s4.w);
                atomicMaxF(&g_pmax[g * HID + c0], m4.x);
                atomicMaxF(&g_pmax[g * HID + c0 + 1], m4.y);
                atomicMaxF(&g_pmax[g * HID + c0 + 2], m4.z);
                atomicMaxF(&g_pmax[g * HID + c0 + 3], m4.w);
                if (lane == 0) atomicAdd(&g_pcnt[g], cnt);
            }
            g = gn;
            s4 = make_float4(0.f, 0.f, 0.f, 0.f);
            m4 = make_float4(-FLT_MAX, -FLT_MAX, -FLT_MAX, -FLT_MAX);
            cnt = 0;
        }
        float4 v[NL];
        float p[NL];
#pragma unroll
        for (int l = 0; l < NL; l++) {
            v[l] = *(const float4*)(&g_hs[l][(size_t)n * HID + c0]);
            p[l] = v[l].x * attc[l].x + v[l].y * attc[l].y +
                   v[l].z * attc[l].z + v[l].w * attc[l].w;
        }
#pragma unroll
        for (int off = 16; off; off >>= 1) {
#pragma unroll
            for (int l = 0; l < NL; l++)
                p[l] += __shfl_xor_sync(0xffffffffu, p[l], off);
        }
        float m = fmaxf(fmaxf(p[0], p[1]), fmaxf(p[2], p[3]));
        float e[NL], tot = 0.f;
#pragma unroll
        for (int l = 0; l < NL; l++) {
            e[l] = expf((p[l] - m) * (1.0f / HID));
            tot += e[l];
        }
        float inv = 1.0f / tot;
        float4 xc = make_float4(0.f, 0.f, 0.f, 0.f);
#pragma unroll
        for (int l = 0; l < NL; l++) {
            float w = e[l] * inv;
            xc.x += w * v[l].x; xc.y += w * v[l].y;
            xc.z += w * v[l].z; xc.w += w * v[l].w;
        }
        s4.x += xc.x; s4.y += xc.y; s4.z += xc.z; s4.w += xc.w;
        m4.x = fmaxf(m4.x, xc.x); m4.y = fmaxf(m4.y, xc.y);
        m4.z = fmaxf(m4.z, xc.z); m4.w = fmaxf(m4.w, xc.w);
        cnt++;
    }
    if (cnt > 0) {
        atomicAdd(&g_psum[g * HID + c0], s4.x);
        atomicAdd(&g_psum[g * HID + c0 + 1], s4.y);
        atomicAdd(&g_psum[g * HID + c0 + 2], s4.z);
        atomicAdd(&g_psum[g * HID + c0 + 3], s4.w);
        atomicMaxF(&g_pmax[g * HID + c0], m4.x);
        atomicMaxF(&g_pmax[g * HID + c0 + 1], m4.y);
        atomicMaxF(&g_pmax[g * HID + c0 + 2], m4.z);
        atomicMaxF(&g_pmax[g * HID + c0 + 3], m4.w);
        if (lane == 0) atomicAdd(&g_pcnt[g], cnt);
    }
}

// ---------------- head ----------------
__global__ void head_kernel(const float* __restrict__ pwraw,
                            const float* __restrict__ fcA_w, const float* __restrict__ fcA_b,
                            const float* __restrict__ ln_g, const float* __restrict__ ln_b,
                            const float* __restrict__ fcB_w, const float* __restrict__ fcB_b,
                            float* __restrict__ out) {
    __shared__ float sp[HID];
    __shared__ float sh[HID];
    __shared__ float red[HID];
    int g = blockIdx.x, c = threadIdx.x;

    float w0 = pwraw[0], w1 = pwraw[1], w2 = pwraw[2];
    float mw = fmaxf(w0, fmaxf(w1, w2));
    float e0 = expf(w0 - mw), e1 = expf(w1 - mw), e2 = expf(w2 - mw);
    float et = 1.0f / (e0 + e1 + e2);
    float pw0 = e0 * et, pw1 = e1 * et, pw2 = e2 * et;

    float cnt = (float)g_pcnt[g];
    float s = g_psum[g * HID + c];
    float mean = s / fmaxf(cnt, 1.0f);
    float mx = (cnt > 0.f) ? g_pmax[g * HID + c] : 0.0f;
    float pooled = s * pw0 + mean * pw1 + mx * pw2;
    sp[c] = pooled;
    __syncthreads();

    float acc = fcA_b[c];
#pragma unroll 8
    for (int k = 0; k < HID; k++) acc += sp[k] * fcA_w[k * HID + c];

    red[c] = acc;
    __syncthreads();
    for (int st = 64; st > 0; st >>= 1) { if (c < st) red[c] += red[c + st]; __syncthreads(); }
    float mu = red[0] * (1.0f / HID);
    __syncthreads();
    float d = acc - mu;
    red[c] = d * d;
    __syncthreads();
    for (int st = 64; st > 0; st >>= 1) { if (c < st) red[c] += red[c + st]; __syncthreads(); }
    float var = red[0] * (1.0f / HID);
    float y = d * rsqrtf(var + 1e-5f) * ln_g[c] + ln_b[c];
    float h = gelu_exact(y) + pooled;
    sh[c] = h;
    __syncthreads();

    if (c < LAT) {
        float o = fcB_b[c];
#pragma unroll 8
        for (int k = 0; k < HID; k++) o += sh[k] * fcB_w[k * LAT + c];
        out[g * LAT + c] = o;
    }
}

// ---------------- launcher ----------------
extern "C" void kernel_launch(void* const* d_in, const int* in_sizes, int n_in,
                              void* d_out, int out_size) {
    const float* x      = (const float*)d_in[0];
    const int*   ei     = (const int*)d_in[1];
    const int*   batch  = (const int*)d_in[2];
    const float* ibn_g  = (const float*)d_in[3];
    const float* ibn_b  = (const float*)d_in[4];
    const float* eps    = (const float*)d_in[5];
    const float* fc1_w  = (const float*)d_in[6];
    const float* fc1_b  = (const float*)d_in[7];
    const float* bn1_g  = (const float*)d_in[8];
    const float* bn1_b  = (const float*)d_in[9];
    const float* fc2_w  = (const float*)d_in[10];
    const float* fc2_b  = (const float*)d_in[11];
    const float* bn_g   = (const float*)d_in[12];
    const float* bn_b   = (const float*)d_in[13];
    const float* att_w  = (const float*)d_in[14];
    const float* pool_w = (const float*)d_in[15];
    const float* fcA_w  = (const float*)d_in[16];
    const float* fcA_b  = (const float*)d_in[17];
    const float* ln_g   = (const float*)d_in[18];
    const float* ln_b   = (const float*)d_in[19];
    const float* fcB_w  = (const float*)d_in[20];
    const float* fcB_b  = (const float*)d_in[21];
    float* out = (float*)d_out;

    const int* srcp = ei;
    const int* dstp = ei + N_EDGES;

    cudaFuncSetAttribute(mma_gemm_kernel<1>, cudaFuncAttributeMaxDynamicSharedMemorySize, TC_SMEM);
    cudaFuncSetAttribute(mma_gemm_kernel<2>, cudaFuncAttributeMaxDynamicSharedMemorySize, TC_SMEM);
    cudaFuncSetAttribute(mma_gemm_kernel<3>, cudaFuncAttributeMaxDynamicSharedMemorySize, TC_SMEM);

    float *p_t, *p_hs;
    cudaGetSymbolAddress((void**)&p_t, g_t);
    cudaGetSymbolAddress((void**)&p_hs, g_hs);

    const int GEMM_GRID = (N_NODES + 63) / 64;          // 782
    const int EW_GRID   = (N_NODES * HID) / (256 * 4);  // 6250
    const int SCAN_GRID = (N_NODES + 1023) / 1024;      // 49
    const int INIT_GRID = (N_GRAPHS * HID + 255) / 256; // 256 -> covers 65536

    zero_init_kernel<<<INIT_GRID, 256>>>();
    wsplit_kernel<<<64, 256>>>(fc1_w, fc2_w);
    colstats_kernel<<<256, 128>>>(x, N_NODES, 0);

    hist_kernel<<<(N_EDGES + 511) / 512, 512>>>(dstp);
    scan1_kernel<<<SCAN_GRID, 1024>>>();
    scan3_kernel<<<SCAN_GRID, 1024>>>();
    scatter_kernel<<<(N_EDGES + 511) / 512, 512>>>(srcp, dstp);

    for (int l = 0; l < NL; l++) {
        int s1 = 1 + 2 * l, s2 = 2 + 2 * l;
        if (l == 0) {
            // GEMM1 layer0: gather raw x + folded input-BN affine; stats -> s1
            mma_gemm_kernel<3><<<GEMM_GRID, 256, TC_SMEM>>>(
                x, 0, fc1_b, p_t, N_NODES, 0, ibn_g, ibn_b, s1, eps, 0);
        } else {
            // GEMM1: gather previous hidden state; stats -> s1
            mma_gemm_kernel<2><<<GEMM_GRID, 256, TC_SMEM>>>(
                p_hs + (size_t)(l - 1) * N_NODES * HID, l * 2, fc1_b + l * HID,
                p_t, N_NODES, 0, nullptr, nullptr, s1, eps, l);
        }
        // GEMM2: fused BN(s1)+GELU on A load, in-place, stats -> s2
        mma_gemm_kernel<1><<<GEMM_GRID, 256, TC_SMEM>>>(
            p_t, l * 2 + 1, fc2_b + l * HID, p_t, N_NODES, s1,
            bn1_g + l * HID, bn1_b + l * HID, s2, eps, l);
        // BN(s2)+GELU -> hidden state l
        bn_apply_kernel<<<EW_GRID, 256>>>(p_t, p_hs + (size_t)l * N_NODES * HID,
                                          s2, bn_g + l * HID, bn_b + l * HID);
    }

    jk_pool_kernel<<<JKP_BLOCKS, 256>>>(batch, att_w);
    head_kernel<<<N_GRAPHS, 128>>>(pool_w, fcA_w, fcA_b, ln_g, ln_b, fcB_w, fcB_b, out);
}

// round 9
// speedup vs baseline: 1.2062x; 1.2062x over previous
#include <cuda_runtime.h>
#include <cuda_bf16.h>
#include <math.h>
#include <float.h>
#include <stdint.h>

#define N_NODES 50000
#define N_EDGES 600000
#define N_GRAPHS 512
#define HID 128
#define LAT 64
#define NL 4
#define NSLOT 10

// ======================= scratch =======================
__device__ float g_h[N_NODES * HID];            // agg output / GEMM1 input
__device__ float g_t[N_NODES * HID];            // GEMM output buffer
__device__ float g_hs[NL][N_NODES * HID];       // per-layer hidden states (JK)
__device__ int   g_deg[N_NODES];
__device__ int   g_ptr[N_NODES + 1];
__device__ int   g_cursor[N_NODES];
__device__ int   g_srclist[N_EDGES];
__device__ int   g_bsum[64];
__device__ float g_sum[NSLOT * HID];
__device__ float g_sumsq[NSLOT * HID];
__device__ float g_psum[N_GRAPHS * HID];
__device__ float g_pmax[N_GRAPHS * HID];
__device__ int   g_pcnt[N_GRAPHS];
// per weight: 32KB hi + 32KB lo, B^T layout [n][k] row-major bf16
__device__ unsigned char g_wsplit[8][65536];

__device__ __forceinline__ float gelu_exact(float x) {
    return 0.5f * x * (1.0f + erff(x * 0.70710678118654752f));
}
__device__ __forceinline__ void atomicMaxF(float* addr, float v) {
    if (__float_as_int(v) >= 0) atomicMax((int*)addr, __float_as_int(v));
    else atomicMin((unsigned int*)addr, __float_as_uint(v));
}
__device__ __forceinline__ uint32_t smem_u32(const void* p) {
    uint32_t a;
    asm("{ .reg .u64 t; cvta.to.shared.u64 t, %1; cvt.u32.u64 %0, t; }" : "=r"(a) : "l"(p));
    return a;
}

#define LDMATRIX_X4(r, addr) \
    asm volatile("ldmatrix.sync.aligned.m8n8.x4.shared.b16 {%0,%1,%2,%3}, [%4];" \
        : "=r"((r)[0]), "=r"((r)[1]), "=r"((r)[2]), "=r"((r)[3]) : "r"(addr))

#define MMA16816(c, a, b) \
    asm volatile("mma.sync.aligned.m16n8k16.row.col.f32.bf16.bf16.f32 " \
        "{%0,%1,%2,%3}, {%4,%5,%6,%7}, {%8,%9}, {%0,%1,%2,%3};" \
        : "+f"((c)[0]), "+f"((c)[1]), "+f"((c)[2]), "+f"((c)[3]) \
        : "r"((a)[0]), "r"((a)[1]), "r"((a)[2]), "r"((a)[3]), "r"((b)[0]), "r"((b)[1]))

// finalize BN stats for `slot` into smem scale/shift (first 128 threads)
__device__ __forceinline__ void finalize_to_smem(int slot, const float* gamma,
                                                 const float* beta,
                                                 float* sScale, float* sShift, int tid) {
    if (tid < HID) {
        const float invN = 1.0f / N_NODES;
        float mean = g_sum[slot * HID + tid] * invN;
        float var  = g_sumsq[slot * HID + tid] * invN - mean * mean;
        float sc = __ldg(&gamma[tid]) * rsqrtf(var + 1e-5f);
        sScale[tid] = sc;
        sShift[tid] = __ldg(&beta[tid]) - mean * sc;
    }
}

// ======================= init (covers pooling buffers: 65536 threads!) ==========
__global__ void zero_init_kernel() {
    int i = blockIdx.x * blockDim.x + threadIdx.x;
    if (i < NSLOT * HID) { g_sum[i] = 0.f; g_sumsq[i] = 0.f; }
    if (i < N_NODES) g_deg[i] = 0;
    if (i < N_GRAPHS * HID) { g_psum[i] = 0.f; g_pmax[i] = -FLT_MAX; }
    if (i < N_GRAPHS) g_pcnt[i] = 0;
}

__global__ void colstats_kernel(const float* __restrict__ A, int M, int slot) {
    int c = threadIdx.x;
    float s = 0.f, s2 = 0.f;
    for (int n = blockIdx.x; n < M; n += gridDim.x) {
        float v = A[n * HID + c];
        s += v; s2 += v * v;
    }
    atomicAdd(&g_sum[slot * HID + c], s);
    atomicAdd(&g_sumsq[slot * HID + c], s2);
}

// BN+GELU apply with inlined finalize (writes hidden state for jk)
__global__ void bn_apply_kernel(const float* __restrict__ in, float* __restrict__ out,
                                int slot, const float* __restrict__ gamma,
                                const float* __restrict__ beta) {
    __shared__ float sScale[HID], sShift[HID];
    int tid = threadIdx.x;
    finalize_to_smem(slot, gamma, beta, sScale, sShift, tid);
    __syncthreads();
    int idx = blockIdx.x * blockDim.x + tid;
    int c4 = idx & 31;
    float4 v  = ((const float4*)in)[idx];
    float4 sc = ((const float4*)sScale)[c4];
    float4 sh = ((const float4*)sShift)[c4];
    v.x = gelu_exact(v.x * sc.x + sh.x);
    v.y = gelu_exact(v.y * sc.y + sh.y);
    v.z = gelu_exact(v.z * sc.z + sh.z);
    v.w = gelu_exact(v.w * sc.w + sh.w);
    ((float4*)out)[idx] = v;
}

// ---------------- CSR build ----------------
__global__ void hist_kernel(const int* __restrict__ dst) {
    int i = blockIdx.x * blockDim.x + threadIdx.x;
    if (i < N_EDGES) atomicAdd(&g_deg[dst[i]], 1);
}

__global__ void scan1_kernel() {     // per-block inclusive scan of degrees
    __shared__ int s[1024];
    int tid = threadIdx.x;
    int i = blockIdx.x * 1024 + tid;
    int v = (i < N_NODES) ? g_deg[i] : 0;
    s[tid] = v;
    __syncthreads();
#pragma unroll
    for (int d = 1; d < 1024; d <<= 1) {
        int t = (tid >= d) ? s[tid - d] : 0;
        __syncthreads();
        s[tid] += t;
        __syncthreads();
    }
    if (i < N_NODES) g_cursor[i] = s[tid];          // inclusive within block
    if (tid == 1023) g_bsum[blockIdx.x] = s[tid];
}

__global__ void scan3_kernel() {     // finalize ptr+cursor (block offset computed locally)
    __shared__ int boff;
    if (threadIdx.x == 0) {
        int s = 0;
        for (int k = 0; k < blockIdx.x; k++) s += g_bsum[k];
        boff = s;
    }
    __syncthreads();
    int i = blockIdx.x * 1024 + threadIdx.x;
    if (i < N_NODES) {
        int p = boff + g_cursor[i] - g_deg[i];
        g_ptr[i] = p;
        g_cursor[i] = p;
    }
    if (i == 0) g_ptr[N_NODES] = N_EDGES;
}

__global__ void scatter_kernel(const int* __restrict__ src, const int* __restrict__ dst) {
    int i = blockIdx.x * blockDim.x + threadIdx.x;
    if (i < N_EDGES) {
        int pos = atomicAdd(&g_cursor[dst[i]], 1);
        g_srclist[pos] = src[i];
    }
}

// ---------------- GIN aggregation (block-per-node, 128 threads/col) ----------------
// L0=1: reads RAW x and folds input-BN affine: sc*((1+eps)x_self + sum x_nb) + (1+eps+deg)*sh
template <int L0>
__global__ void agg_kernel(const float* __restrict__ in, int layer,
                           const float* __restrict__ eps,
                           const float* __restrict__ gamma, const float* __restrict__ beta) {
    __shared__ float sScale[HID], sShift[HID];
    int n = blockIdx.x;
    int c = threadIdx.x;
    if (L0) {
        finalize_to_smem(0, gamma, beta, sScale, sShift, c);
        __syncthreads();
    }
    float ev = __ldg(&eps[layer]);
    float op = 1.0f + ev;
    float acc = op * in[n * HID + c];
    int b = g_ptr[n], e = g_ptr[n + 1];
    int j = b;
    for (; j + 3 < e; j += 4) {
        int s0 = g_srclist[j], s1 = g_srclist[j + 1];
        int s2 = g_srclist[j + 2], s3 = g_srclist[j + 3];
        float v0 = __ldg(&in[s0 * HID + c]);
        float v1 = __ldg(&in[s1 * HID + c]);
        float v2 = __ldg(&in[s2 * HID + c]);
        float v3 = __ldg(&in[s3 * HID + c]);
        acc += (v0 + v1) + (v2 + v3);
    }
    for (; j < e; j++) acc += __ldg(&in[g_srclist[j] * HID + c]);
    if (L0) acc = sScale[c] * acc + (op + (float)(e - b)) * sShift[c];
    g_h[n * HID + c] = acc;
}

// ---------------- weight split prep: B^T[n][k] hi/lo bf16 ----------------
__global__ void wsplit_kernel(const float* __restrict__ fc1_w, const float* __restrict__ fc2_w) {
    int w = blockIdx.x >> 3;
    int l = w >> 1, which = w & 1;
    const float* W = (which ? fc2_w : fc1_w) + l * HID * HID;
    __nv_bfloat16* bh = (__nv_bfloat16*)(g_wsplit[w]);
    __nv_bfloat16* bl = (__nv_bfloat16*)(g_wsplit[w] + 32768);
    int chunk = blockIdx.x & 7;
    for (int i = threadIdx.x + chunk * 2048; i < (chunk + 1) * 2048; i += 256) {
        int n = i >> 7, k = i & 127;
        float v = W[k * HID + n];
        __nv_bfloat16 hi = __float2bfloat16_rn(v);
        bh[n * 128 + k] = hi;
        bl[n * 128 + k] = __float2bfloat16_rn(v - __bfloat162float(hi));
    }
}

// ---------------- HMMA GEMM 64x128 tile, 2 CTAs/SM (R7-proven) ----------------
#define APAD 136
#define AT_BYTES (64 * APAD * 2)         // 17408
#define BT_BYTES (128 * APAD * 2)        // 34816
#define SM_AH 0
#define SM_AL AT_BYTES
#define SM_BH (2 * AT_BYTES)
#define SM_BL (2 * AT_BYTES + BT_BYTES)
#define SM_SC (2 * AT_BYTES + 2 * BT_BYTES)   // 104448
#define SM_SH (SM_SC + 512)
#define TC_SMEM (SM_SC + 1024)               // 105472 -> 2 CTAs/SM

template <int PRE>
__global__ void __launch_bounds__(256, 2)
mma_gemm_kernel(const float* __restrict__ A, int widx, const float* __restrict__ bias,
                float* __restrict__ C, int M, int slot,
                const float* __restrict__ gamma, const float* __restrict__ beta,
                int oslot) {
    extern __shared__ unsigned char smem[];
    int tid = threadIdx.x, lane = tid & 31, wid = tid >> 5;
    int m0 = blockIdx.x * 64;
    uint32_t sb = smem_u32(smem);
    float* sScale = (float*)(smem + SM_SC);
    float* sShift = (float*)(smem + SM_SH);

    if (PRE) {
        finalize_to_smem(slot, gamma, beta, sScale, sShift, tid);
        __syncthreads();
    }

    // ---- B: copy pre-split B^T (hi+lo) with row padding ----
    {
        const uint4* srcH = (const uint4*)(g_wsplit[widx]);
        const uint4* srcL = (const uint4*)(g_wsplit[widx] + 32768);
#pragma unroll
        for (int it = 0; it < 8; it++) {
            int i = tid + it * 256;
            int n = i >> 4, s = i & 15;
            *(uint4*)(smem + SM_BH + n * (APAD * 2) + s * 16) = __ldg(srcH + i);
            *(uint4*)(smem + SM_BL + n * (APAD * 2) + s * 16) = __ldg(srcL + i);
        }
    }

    // ---- A: load (4 threads/row), optional BN+GELU, split hi/lo ----
    {
        int r = tid >> 2, qt = tid & 3;
        bool valid = (m0 + r) < M;
        const float4* Arow = (const float4*)(A + (size_t)(m0 + r) * HID + qt * 32);
#pragma unroll
        for (int jj = 0; jj < 8; jj++) {
            int col = qt * 32 + jj * 4;
            float4 v = valid ? __ldg(Arow + jj) : make_float4(0.f, 0.f, 0.f, 0.f);
            if (PRE) {
                float4 sc = ((const float4*)sScale)[col >> 2];
                float4 sh = ((const float4*)sShift)[col >> 2];
                v.x = gelu_exact(v.x * sc.x + sh.x);
                v.y = gelu_exact(v.y * sc.y + sh.y);
                v.z = gelu_exact(v.z * sc.z + sh.z);
                v.w = gelu_exact(v.w * sc.w + sh.w);
            }
            __nv_bfloat16 h0 = __float2bfloat16_rn(v.x), h1 = __float2bfloat16_rn(v.y);
            __nv_bfloat16 h2 = __float2bfloat16_rn(v.z), h3 = __float2bfloat16_rn(v.w);
            float l0 = v.x - __bfloat162float(h0), l1 = v.y - __bfloat162float(h1);
            float l2 = v.z - __bfloat162float(h2), l3 = v.w - __bfloat162float(h3);
            uint2 hp, lp;
            hp.x = (uint32_t)__bfloat16_as_ushort(h0) | ((uint32_t)__bfloat16_as_ushort(h1) << 16);
            hp.y = (uint32_t)__bfloat16_as_ushort(h2) | ((uint32_t)__bfloat16_as_ushort(h3) << 16);
            lp.x = (uint32_t)__bfloat16_as_ushort(__float2bfloat16_rn(l0)) |
                   ((uint32_t)__bfloat16_as_ushort(__float2bfloat16_rn(l1)) << 16);
            lp.y = (uint32_t)__bfloat16_as_ushort(__float2bfloat16_rn(l2)) |
                   ((uint32_t)__bfloat16_as_ushort(__float2bfloat16_rn(l3)) << 16);
            uint32_t off = r * (APAD * 2) + col * 2;
            *(uint2*)(smem + SM_AH + off) = hp;
            *(uint2*)(smem + SM_AL + off) = lp;
        }
    }
    __syncthreads();

    // ---- MMA mainloop: warp grid 2(M) x 4(N), warp tile 32x32 ----
    int wm = wid & 1, wn = wid >> 1;
    int mbase = wm * 32, nbase = wn * 32;
    float acc[2][4][4];
#pragma unroll
    for (int i = 0; i < 2; i++)
#pragma unroll
        for (int j = 0; j < 4; j++)
#pragma unroll
            for (int c = 0; c < 4; c++) acc[i][j][c] = 0.f;

    int q = lane >> 3, riq = lane & 7;
#pragma unroll
    for (int ks = 0; ks < 8; ks++) {
        uint32_t ah[2][4], al[2][4], bh[4][2], bl[4][2];
#pragma unroll
        for (int i = 0; i < 2; i++) {
            int row = mbase + i * 16 + (q & 1) * 8 + riq;
            int kb = ks * 16 + (q >> 1) * 8;
            uint32_t addr = sb + SM_AH + row * (APAD * 2) + kb * 2;
            LDMATRIX_X4(ah[i], addr);
            LDMATRIX_X4(al[i], addr + AT_BYTES);
        }
#pragma unroll
        for (int j = 0; j < 2; j++) {
            int n = nbase + j * 16 + (q >> 1) * 8 + riq;
            int kb = ks * 16 + (q & 1) * 8;
            uint32_t addr = sb + SM_BH + n * (APAD * 2) + kb * 2;
            uint32_t t4[4];
            LDMATRIX_X4(t4, addr);
            bh[j * 2][0] = t4[0]; bh[j * 2][1] = t4[1];
            bh[j * 2 + 1][0] = t4[2]; bh[j * 2 + 1][1] = t4[3];
            LDMATRIX_X4(t4, addr + BT_BYTES);
            bl[j * 2][0] = t4[0]; bl[j * 2][1] = t4[1];
            bl[j * 2 + 1][0] = t4[2]; bl[j * 2 + 1][1] = t4[3];
        }
#pragma unroll
        for (int i = 0; i < 2; i++)
#pragma unroll
            for (int j = 0; j < 4; j++) {
                MMA16816(acc[i][j], ah[i], bh[j]);
                MMA16816(acc[i][j], ah[i], bl[j]);
                MMA16816(acc[i][j], al[i], bh[j]);
            }
    }
    __syncthreads();   // tiles consumed; reuse smem for C staging

    // ---- epilogue: regs -> smem (+bias) -> coalesced STG + fused stats ----
    float* sC = (float*)smem;   // 64 x 132 floats (fits in Ah+Al region)
    int g = lane >> 2, tc = (lane & 3) * 2;
#pragma unroll
    for (int i = 0; i < 2; i++) {
        int row0 = mbase + i * 16 + g;
#pragma unroll
        for (int j = 0; j < 4; j++) {
            int col = nbase + j * 8 + tc;
            float b0 = __ldg(&bias[col]), b1 = __ldg(&bias[col + 1]);
            sC[row0 * 132 + col]           = acc[i][j][0] + b0;
            sC[row0 * 132 + col + 1]       = acc[i][j][1] + b1;
            sC[(row0 + 8) * 132 + col]     = acc[i][j][2] + b0;
            sC[(row0 + 8) * 132 + col + 1] = acc[i][j][3] + b1;
        }
    }
    __syncthreads();

    {
        int r2 = tid >> 2, qt = tid & 3;
        if (m0 + r2 < M) {
            float4* dst = (float4*)(C + (size_t)(m0 + r2) * HID + qt * 32);
            const float4* src = (const float4*)(sC + r2 * 132 + qt * 32);
#pragma unroll
            for (int i = 0; i < 8; i++) dst[i] = src[i];
        }
    }

    {
        int nrows = min(64, M - m0);
        int c = tid & 127;
        int rbeg = (tid >> 7) * 32;
        int rend = min(rbeg + 32, nrows);
        float s = 0.f, s2 = 0.f;
        for (int rr = rbeg; rr < rend; rr++) {
            float v = sC[rr * 132 + c];
            s += v; s2 += v * v;
        }
        atomicAdd(&g_sum[oslot * HID + c], s);
        atomicAdd(&g_sumsq[oslot * HID + c], s2);
    }
}

// ---------------- fused JK attention + pooling (warp-autonomous) ----------------
#define JKP_BLOCKS 500
#define JKP_WARPS (JKP_BLOCKS * 8)
__global__ void jk_pool_kernel(const int* __restrict__ batch, const float* __restrict__ att) {
    int wgid = blockIdx.x * 8 + (threadIdx.x >> 5);
    int lane = threadIdx.x & 31;
    const int CH = (N_NODES + JKP_WARPS - 1) / JKP_WARPS;   // 13
    int n0 = wgid * CH, n1 = min(n0 + CH, N_NODES);
    if (n0 >= n1) return;
    int c0 = lane * 4;

    float4 attc[NL];
#pragma unroll
    for (int l = 0; l < NL; l++)
        attc[l] = __ldg((const float4*)(att + l * HID) + lane);

    int g = __ldg(&batch[n0]);
    float4 s4 = make_float4(0.f, 0.f, 0.f, 0.f);
    float4 m4 = make_float4(-FLT_MAX, -FLT_MAX, -FLT_MAX, -FLT_MAX);
    int cnt = 0;

    for (int n = n0; n < n1; n++) {
        int gn = __ldg(&batch[n]);
        if (gn != g) {
            if (cnt > 0) {
                atomicAdd(&g_psum[g * HID + c0], s4.x);
                atomicAdd(&g_psum[g * HID + c0 + 1], s4.y);
                atomicAdd(&g_psum[g * HID + c0 + 2], s4.z);
                atomicAdd(&g_psum[g * HID + c0 + 3], s4.w);
                atomicMaxF(&g_pmax[g * HID + c0], m4.x);
                atomicMaxF(&g_pmax[g * HID + c0 + 1], m4.y);
                atomicMaxF(&g_pmax[g * HID + c0 + 2], m4.z);
                atomicMaxF(&g_pmax[g * HID + c0 + 3], m4.w);
                if (lane == 0) atomicAdd(&g_pcnt[g], cnt);
            }
            g = gn;
            s4 = make_float4(0.f, 0.f, 0.f, 0.f);
            m4 = make_float4(-FLT_MAX, -FLT_MAX, -FLT_MAX, -FLT_MAX);
            cnt = 0;
        }
        float4 v[NL];
        float p[NL];
#pragma unroll
        for (int l = 0; l < NL; l++) {
            v[l] = *(const float4*)(&g_hs[l][(size_t)n * HID + c0]);
            p[l] = v[l].x * attc[l].x + v[l].y * attc[l].y +
                   v[l].z * attc[l].z + v[l].w * attc[l].w;
        }
#pragma unroll
        for (int off = 16; off; off >>= 1) {
#pragma unroll
            for (int l = 0; l < NL; l++)
                p[l] += __shfl_xor_sync(0xffffffffu, p[l], off);
        }
        float m = fmaxf(fmaxf(p[0], p[1]), fmaxf(p[2], p[3]));
        float e[NL], tot = 0.f;
#pragma unroll
        for (int l = 0; l < NL; l++) {
            e[l] = expf((p[l] - m) * (1.0f / HID));
            tot += e[l];
        }
        float inv = 1.0f / tot;
        float4 xc = make_float4(0.f, 0.f, 0.f, 0.f);
#pragma unroll
        for (int l = 0; l < NL; l++) {
            float w = e[l] * inv;
            xc.x += w * v[l].x; xc.y += w * v[l].y;
            xc.z += w * v[l].z; xc.w += w * v[l].w;
        }
        s4.x += xc.x; s4.y += xc.y; s4.z += xc.z; s4.w += xc.w;
        m4.x = fmaxf(m4.x, xc.x); m4.y = fmaxf(m4.y, xc.y);
        m4.z = fmaxf(m4.z, xc.z); m4.w = fmaxf(m4.w, xc.w);
        cnt++;
    }
    if (cnt > 0) {
        atomicAdd(&g_psum[g * HID + c0], s4.x);
        atomicAdd(&g_psum[g * HID + c0 + 1], s4.y);
        atomicAdd(&g_psum[g * HID + c0 + 2], s4.z);
        atomicAdd(&g_psum[g * HID + c0 + 3], s4.w);
        atomicMaxF(&g_pmax[g * HID + c0], m4.x);
        atomicMaxF(&g_pmax[g * HID + c0 + 1], m4.y);
        atomicMaxF(&g_pmax[g * HID + c0 + 2], m4.z);
        atomicMaxF(&g_pmax[g * HID + c0 + 3], m4.w);
        if (lane == 0) atomicAdd(&g_pcnt[g], cnt);
    }
}

// ---------------- head ----------------
__global__ void head_kernel(const float* __restrict__ pwraw,
                            const float* __restrict__ fcA_w, const float* __restrict__ fcA_b,
                            const float* __restrict__ ln_g, const float* __restrict__ ln_b,
                            const float* __restrict__ fcB_w, const float* __restrict__ fcB_b,
                            float* __restrict__ out) {
    __shared__ float sp[HID];
    __shared__ float sh[HID];
    __shared__ float red[HID];
    int g = blockIdx.x, c = threadIdx.x;

    float w0 = pwraw[0], w1 = pwraw[1], w2 = pwraw[2];
    float mw = fmaxf(w0, fmaxf(w1, w2));
    float e0 = expf(w0 - mw), e1 = expf(w1 - mw), e2 = expf(w2 - mw);
    float et = 1.0f / (e0 + e1 + e2);
    float pw0 = e0 * et, pw1 = e1 * et, pw2 = e2 * et;

    float cnt = (float)g_pcnt[g];
    float s = g_psum[g * HID + c];
    float mean = s / fmaxf(cnt, 1.0f);
    float mx = (cnt > 0.f) ? g_pmax[g * HID + c] : 0.0f;
    float pooled = s * pw0 + mean * pw1 + mx * pw2;
    sp[c] = pooled;
    __syncthreads();

    float acc = fcA_b[c];
#pragma unroll 8
    for (int k = 0; k < HID; k++) acc += sp[k] * fcA_w[k * HID + c];

    red[c] = acc;
    __syncthreads();
    for (int st = 64; st > 0; st >>= 1) { if (c < st) red[c] += red[c + st]; __syncthreads(); }
    float mu = red[0] * (1.0f / HID);
    __syncthreads();
    float d = acc - mu;
    red[c] = d * d;
    __syncthreads();
    for (int st = 64; st > 0; st >>= 1) { if (c < st) red[c] += red[c + st]; __syncthreads(); }
    float var = red[0] * (1.0f / HID);
    float y = d * rsqrtf(var + 1e-5f) * ln_g[c] + ln_b[c];
    float h = gelu_exact(y) + pooled;
    sh[c] = h;
    __syncthreads();

    if (c < LAT) {
        float o = fcB_b[c];
#pragma unroll 8
        for (int k = 0; k < HID; k++) o += sh[k] * fcB_w[k * LAT + c];
        out[g * LAT + c] = o;
    }
}

// ---------------- launcher ----------------
extern "C" void kernel_launch(void* const* d_in, const int* in_sizes, int n_in,
                              void* d_out, int out_size) {
    const float* x      = (const float*)d_in[0];
    const int*   ei     = (const int*)d_in[1];
    const int*   batch  = (const int*)d_in[2];
    const float* ibn_g  = (const float*)d_in[3];
    const float* ibn_b  = (const float*)d_in[4];
    const float* eps    = (const float*)d_in[5];
    const float* fc1_w  = (const float*)d_in[6];
    const float* fc1_b  = (const float*)d_in[7];
    const float* bn1_g  = (const float*)d_in[8];
    const float* bn1_b  = (const float*)d_in[9];
    const float* fc2_w  = (const float*)d_in[10];
    const float* fc2_b  = (const float*)d_in[11];
    const float* bn_g   = (const float*)d_in[12];
    const float* bn_b   = (const float*)d_in[13];
    const float* att_w  = (const float*)d_in[14];
    const float* pool_w = (const float*)d_in[15];
    const float* fcA_w  = (const float*)d_in[16];
    const float* fcA_b  = (const float*)d_in[17];
    const float* ln_g   = (const float*)d_in[18];
    const float* ln_b   = (const float*)d_in[19];
    const float* fcB_w  = (const float*)d_in[20];
    const float* fcB_b  = (const float*)d_in[21];
    float* out = (float*)d_out;

    const int* srcp = ei;
    const int* dstp = ei + N_EDGES;

    cudaFuncSetAttribute(mma_gemm_kernel<0>, cudaFuncAttributeMaxDynamicSharedMemorySize, TC_SMEM);
    cudaFuncSetAttribute(mma_gemm_kernel<1>, cudaFuncAttributeMaxDynamicSharedMemorySize, TC_SMEM);

    float *p_h, *p_t, *p_hs;
    cudaGetSymbolAddress((void**)&p_h, g_h);
    cudaGetSymbolAddress((void**)&p_t, g_t);
    cudaGetSymbolAddress((void**)&p_hs, g_hs);

    const int GEMM_GRID = (N_NODES + 63) / 64;          // 782
    const int EW_GRID   = (N_NODES * HID) / (256 * 4);  // 6250
    const int SCAN_GRID = (N_NODES + 1023) / 1024;      // 49
    const int INIT_GRID = (N_GRAPHS * HID + 255) / 256; // 256 -> covers 65536

    zero_init_kernel<<<INIT_GRID, 256>>>();
    wsplit_kernel<<<64, 256>>>(fc1_w, fc2_w);
    colstats_kernel<<<256, 128>>>(x, N_NODES, 0);   // input BN stats (raw x)

    hist_kernel<<<(N_EDGES + 511) / 512, 512>>>(dstp);
    scan1_kernel<<<SCAN_GRID, 1024>>>();
    scan3_kernel<<<SCAN_GRID, 1024>>>();
    scatter_kernel<<<(N_EDGES + 511) / 512, 512>>>(srcp, dstp);

    for (int l = 0; l < NL; l++) {
        int s1 = 1 + 2 * l, s2 = 2 + 2 * l;
        if (l == 0) {
            // agg on RAW x with folded input-BN affine (deletes input bn_apply pass)
            agg_kernel<1><<<N_NODES, 128>>>(x, 0, eps, ibn_g, ibn_b);
        } else {
            agg_kernel<0><<<N_NODES, 128>>>(p_hs + (size_t)(l - 1) * N_NODES * HID,
                                            l, eps, nullptr, nullptr);
        }
        mma_gemm_kernel<0><<<GEMM_GRID, 256, TC_SMEM>>>(p_h, l * 2 + 0, fc1_b + l * HID,
                                                        p_t, N_NODES, 0, nullptr, nullptr, s1);
        mma_gemm_kernel<1><<<GEMM_GRID, 256, TC_SMEM>>>(p_t, l * 2 + 1, fc2_b + l * HID,
                                                        p_t, N_NODES, s1,
                                                        bn1_g + l * HID, bn1_b + l * HID, s2);
        bn_apply_kernel<<<EW_GRID, 256>>>(p_t, p_hs + (size_t)l * N_NODES * HID,
                                          s2, bn_g + l * HID, bn_b + l * HID);
    }

    jk_pool_kernel<<<JKP_BLOCKS, 256>>>(batch, att_w);
    head_kernel<<<N_GRAPHS, 128>>>(pool_w, fcA_w, fcA_b, ln_g, ln_b, fcB_w, fcB_b, out);
}

// round 10
// speedup vs baseline: 1.4044x; 1.1643x over previous
#include <cuda_runtime.h>
#include <cuda_bf16.h>
#include <math.h>
#include <float.h>
#include <stdint.h>

#define N_NODES 50000
#define N_EDGES 600000
#define N_GRAPHS 512
#define HID 128
#define LAT 64
#define NL 4
#define NSLOT 10
#define NTILES 782          // ceil(N_NODES/64)
#define PGRID 296           // 2 CTAs x 148 SMs (persistent GEMM grid)

// ======================= scratch =======================
__device__ float g_h[N_NODES * HID];            // agg output / GEMM1 input
__device__ float g_t[N_NODES * HID];            // GEMM output buffer
__device__ float g_hs[NL][N_NODES * HID];       // per-layer hidden states (JK)
__device__ int   g_deg[N_NODES];
__device__ int   g_ptr[N_NODES + 1];
__device__ int   g_cursor[N_NODES];
__device__ int   g_srclist[N_EDGES];
__device__ int   g_bsum[64];
__device__ float g_sum[NSLOT * HID];
__device__ float g_sumsq[NSLOT * HID];
__device__ float g_psum[N_GRAPHS * HID];
__device__ float g_pmax[N_GRAPHS * HID];
__device__ int   g_pcnt[N_GRAPHS];
__device__ int   g_tile_ctr[8];                 // per-GEMM dynamic tile counters
// per weight: 32KB hi + 32KB lo, B^T layout [n][k] row-major bf16
__device__ unsigned char g_wsplit[8][65536];

__device__ __forceinline__ float gelu_exact(float x) {
    return 0.5f * x * (1.0f + erff(x * 0.70710678118654752f));
}
__device__ __forceinline__ void atomicMaxF(float* addr, float v) {
    if (__float_as_int(v) >= 0) atomicMax((int*)addr, __float_as_int(v));
    else atomicMin((unsigned int*)addr, __float_as_uint(v));
}
__device__ __forceinline__ uint32_t smem_u32(const void* p) {
    uint32_t a;
    asm("{ .reg .u64 t; cvta.to.shared.u64 t, %1; cvt.u32.u64 %0, t; }" : "=r"(a) : "l"(p));
    return a;
}

#define LDMATRIX_X4(r, addr) \
    asm volatile("ldmatrix.sync.aligned.m8n8.x4.shared.b16 {%0,%1,%2,%3}, [%4];" \
        : "=r"((r)[0]), "=r"((r)[1]), "=r"((r)[2]), "=r"((r)[3]) : "r"(addr))

#define MMA16816(c, a, b) \
    asm volatile("mma.sync.aligned.m16n8k16.row.col.f32.bf16.bf16.f32 " \
        "{%0,%1,%2,%3}, {%4,%5,%6,%7}, {%8,%9}, {%0,%1,%2,%3};" \
        : "+f"((c)[0]), "+f"((c)[1]), "+f"((c)[2]), "+f"((c)[3]) \
        : "r"((a)[0]), "r"((a)[1]), "r"((a)[2]), "r"((a)[3]), "r"((b)[0]), "r"((b)[1]))

// finalize BN stats for `slot` into smem scale/shift (first 128 threads)
__device__ __forceinline__ void finalize_to_smem(int slot, const float* gamma,
                                                 const float* beta,
                                                 float* sScale, float* sShift, int tid) {
    if (tid < HID) {
        const float invN = 1.0f / N_NODES;
        float mean = g_sum[slot * HID + tid] * invN;
        float var  = g_sumsq[slot * HID + tid] * invN - mean * mean;
        float sc = __ldg(&gamma[tid]) * rsqrtf(var + 1e-5f);
        sScale[tid] = sc;
        sShift[tid] = __ldg(&beta[tid]) - mean * sc;
    }
}

// ======== merged prep: zero-init + weight split + input colstats (one launch) =====
#define PREP_ZERO 256
#define PREP_WS 64
#define PREP_CS 256
__global__ void prep_kernel(const float* __restrict__ x,
                            const float* __restrict__ fc1_w,
                            const float* __restrict__ fc2_w) {
    int b = blockIdx.x, tid = threadIdx.x;
    if (b < PREP_ZERO) {
        int i = b * 256 + tid;
        if (i < NSLOT * HID) { g_sum[i] = 0.f; g_sumsq[i] = 0.f; }
        if (i < N_NODES) g_deg[i] = 0;
        if (i < N_GRAPHS * HID) { g_psum[i] = 0.f; g_pmax[i] = -FLT_MAX; }
        if (i < N_GRAPHS) g_pcnt[i] = 0;
        if (i < 8) g_tile_ctr[i] = PGRID;      // persistent GEMM counters
    } else if (b < PREP_ZERO + PREP_WS) {
        int bb = b - PREP_ZERO;
        int w = bb >> 3;
        int l = w >> 1, which = w & 1;
        const float* W = (which ? fc2_w : fc1_w) + l * HID * HID;
        __nv_bfloat16* bh = (__nv_bfloat16*)(g_wsplit[w]);
        __nv_bfloat16* bl = (__nv_bfloat16*)(g_wsplit[w] + 32768);
        int chunk = bb & 7;
        for (int i = tid + chunk * 2048; i < (chunk + 1) * 2048; i += 256) {
            int n = i >> 7, k = i & 127;
            float v = W[k * HID + n];
            __nv_bfloat16 hi = __float2bfloat16_rn(v);
            bh[n * 128 + k] = hi;
            bl[n * 128 + k] = __float2bfloat16_rn(v - __bfloat162float(hi));
        }
    } else {
        // input colstats on raw x -> slot 0
        int p = b - (PREP_ZERO + PREP_WS);     // 0..255
        int c = tid & 127;
        float s = 0.f, s2 = 0.f;
        for (int n = p * 2 + (tid >> 7); n < N_NODES; n += 512) {
            float v = x[n * HID + c];
            s += v; s2 += v * v;
        }
        atomicAdd(&g_sum[c], s);
        atomicAdd(&g_sumsq[c], s2);
    }
}

// BN+GELU apply with inlined finalize (2 float4 per thread)
__global__ void bn_apply_kernel(const float* __restrict__ in, float* __restrict__ out,
                                int slot, const float* __restrict__ gamma,
                                const float* __restrict__ beta) {
    __shared__ float sScale[HID], sShift[HID];
    int tid = threadIdx.x;
    finalize_to_smem(slot, gamma, beta, sScale, sShift, tid);
    __syncthreads();
    int base = (blockIdx.x * 256 + tid) * 2;
#pragma unroll
    for (int k = 0; k < 2; k++) {
        int idx = base + k;
        int c4 = idx & 31;
        float4 v  = ((const float4*)in)[idx];
        float4 sc = ((const float4*)sScale)[c4];
        float4 sh = ((const float4*)sShift)[c4];
        v.x = gelu_exact(v.x * sc.x + sh.x);
        v.y = gelu_exact(v.y * sc.y + sh.y);
        v.z = gelu_exact(v.z * sc.z + sh.z);
        v.w = gelu_exact(v.w * sc.w + sh.w);
        ((float4*)out)[idx] = v;
    }
}

// ---------------- CSR build ----------------
__global__ void hist_kernel(const int* __restrict__ dst) {
    int i = blockIdx.x * blockDim.x + threadIdx.x;
    if (i < N_EDGES) atomicAdd(&g_deg[dst[i]], 1);
}

__global__ void scan1_kernel() {     // per-block inclusive scan of degrees
    __shared__ int s[1024];
    int tid = threadIdx.x;
    int i = blockIdx.x * 1024 + tid;
    int v = (i < N_NODES) ? g_deg[i] : 0;
    s[tid] = v;
    __syncthreads();
#pragma unroll
    for (int d = 1; d < 1024; d <<= 1) {
        int t = (tid >= d) ? s[tid - d] : 0;
        __syncthreads();
        s[tid] += t;
        __syncthreads();
    }
    if (i < N_NODES) g_cursor[i] = s[tid];
    if (tid == 1023) g_bsum[blockIdx.x] = s[tid];
}

__global__ void scan3_kernel() {     // finalize ptr+cursor
    __shared__ int boff;
    if (threadIdx.x == 0) {
        int s = 0;
        for (int k = 0; k < blockIdx.x; k++) s += g_bsum[k];
        boff = s;
    }
    __syncthreads();
    int i = blockIdx.x * 1024 + threadIdx.x;
    if (i < N_NODES) {
        int p = boff + g_cursor[i] - g_deg[i];
        g_ptr[i] = p;
        g_cursor[i] = p;
    }
    if (i == 0) g_ptr[N_NODES] = N_EDGES;
}

__global__ void scatter_kernel(const int* __restrict__ src, const int* __restrict__ dst) {
    int i = blockIdx.x * blockDim.x + threadIdx.x;
    if (i < N_EDGES) {
        int pos = atomicAdd(&g_cursor[dst[i]], 1);
        g_srclist[pos] = src[i];
    }
}

// ---------------- GIN aggregation (block-per-node) ----------------
template <int L0>
__global__ void agg_kernel(const float* __restrict__ in, int layer,
                           const float* __restrict__ eps,
                           const float* __restrict__ gamma, const float* __restrict__ beta) {
    __shared__ float sScale[HID], sShift[HID];
    int n = blockIdx.x;
    int c = threadIdx.x;
    if (L0) {
        finalize_to_smem(0, gamma, beta, sScale, sShift, c);
        __syncthreads();
    }
    float ev = __ldg(&eps[layer]);
    float op = 1.0f + ev;
    float acc = op * in[n * HID + c];
    int b = g_ptr[n], e = g_ptr[n + 1];
    int j = b;
    for (; j + 3 < e; j += 4) {
        int s0 = g_srclist[j], s1 = g_srclist[j + 1];
        int s2 = g_srclist[j + 2], s3 = g_srclist[j + 3];
        float v0 = __ldg(&in[s0 * HID + c]);
        float v1 = __ldg(&in[s1 * HID + c]);
        float v2 = __ldg(&in[s2 * HID + c]);
        float v3 = __ldg(&in[s3 * HID + c]);
        acc += (v0 + v1) + (v2 + v3);
    }
    for (; j < e; j++) acc += __ldg(&in[g_srclist[j] * HID + c]);
    if (L0) acc = sScale[c] * acc + (op + (float)(e - b)) * sShift[c];
    g_h[n * HID + c] = acc;
}

// ---------------- persistent HMMA GEMM, dynamic tile-stealing ----------------
#define APAD 136
#define AT_BYTES (64 * APAD * 2)         // 17408
#define BT_BYTES (128 * APAD * 2)        // 34816
#define SM_AH 0
#define SM_AL AT_BYTES
#define SM_BH (2 * AT_BYTES)
#define SM_BL (2 * AT_BYTES + BT_BYTES)
#define SM_SC (2 * AT_BYTES + 2 * BT_BYTES)   // 104448
#define SM_SH (SM_SC + 512)
#define TC_SMEM (SM_SC + 1024)               // 105472 -> 2 CTAs/SM

template <int PRE>
__global__ void __launch_bounds__(256, 2)
mma_gemm_kernel(const float* __restrict__ A, int widx, const float* __restrict__ bias,
                float* __restrict__ C, int M, int slot,
                const float* __restrict__ gamma, const float* __restrict__ beta,
                int oslot) {
    extern __shared__ unsigned char smem[];
    __shared__ int s_tile;
    int tid = threadIdx.x, lane = tid & 31, wid = tid >> 5;
    uint32_t sb = smem_u32(smem);
    float* sScale = (float*)(smem + SM_SC);
    float* sShift = (float*)(smem + SM_SH);

    if (PRE) finalize_to_smem(slot, gamma, beta, sScale, sShift, tid);

    // ---- B: copy pre-split B^T (hi+lo) ONCE per persistent CTA ----
    {
        const uint4* srcH = (const uint4*)(g_wsplit[widx]);
        const uint4* srcL = (const uint4*)(g_wsplit[widx] + 32768);
#pragma unroll
        for (int it = 0; it < 8; it++) {
            int i = tid + it * 256;
            int n = i >> 4, s = i & 15;
            *(uint4*)(smem + SM_BH + n * (APAD * 2) + s * 16) = __ldg(srcH + i);
            *(uint4*)(smem + SM_BL + n * (APAD * 2) + s * 16) = __ldg(srcL + i);
        }
    }

    int t = blockIdx.x;                    // first tile static, rest dynamic
    while (t < NTILES) {
        int m0 = t * 64;
        __syncthreads();   // B/sScale visible; prior tile's sC reads complete

        // ---- A: load (4 threads/row), optional BN+GELU, split hi/lo ----
        {
            int r = tid >> 2, qt = tid & 3;
            bool valid = (m0 + r) < M;
            const float4* Arow = (const float4*)(A + (size_t)(m0 + r) * HID + qt * 32);
#pragma unroll
            for (int jj = 0; jj < 8; jj++) {
                int col = qt * 32 + jj * 4;
                float4 v = valid ? __ldg(Arow + jj) : make_float4(0.f, 0.f, 0.f, 0.f);
                if (PRE) {
                    float4 sc = ((const float4*)sScale)[col >> 2];
                    float4 sh = ((const float4*)sShift)[col >> 2];
                    v.x = gelu_exact(v.x * sc.x + sh.x);
                    v.y = gelu_exact(v.y * sc.y + sh.y);
                    v.z = gelu_exact(v.z * sc.z + sh.z);
                    v.w = gelu_exact(v.w * sc.w + sh.w);
                }
                __nv_bfloat16 h0 = __float2bfloat16_rn(v.x), h1 = __float2bfloat16_rn(v.y);
                __nv_bfloat16 h2 = __float2bfloat16_rn(v.z), h3 = __float2bfloat16_rn(v.w);
                float l0 = v.x - __bfloat162float(h0), l1 = v.y - __bfloat162float(h1);
                float l2 = v.z - __bfloat162float(h2), l3 = v.w - __bfloat162float(h3);
                uint2 hp, lp;
                hp.x = (uint32_t)__bfloat16_as_ushort(h0) | ((uint32_t)__bfloat16_as_ushort(h1) << 16);
                hp.y = (uint32_t)__bfloat16_as_ushort(h2) | ((uint32_t)__bfloat16_as_ushort(h3) << 16);
                lp.x = (uint32_t)__bfloat16_as_ushort(__float2bfloat16_rn(l0)) |
                       ((uint32_t)__bfloat16_as_ushort(__float2bfloat16_rn(l1)) << 16);
                lp.y = (uint32_t)__bfloat16_as_ushort(__float2bfloat16_rn(l2)) |
                       ((uint32_t)__bfloat16_as_ushort(__float2bfloat16_rn(l3)) << 16);
                uint32_t off = r * (APAD * 2) + col * 2;
                *(uint2*)(smem + SM_AH + off) = hp;
                *(uint2*)(smem + SM_AL + off) = lp;
            }
        }
        __syncthreads();

        // ---- MMA mainloop: warp grid 2(M) x 4(N), warp tile 32x32 ----
        int wm = wid & 1, wn = wid >> 1;
        int mbase = wm * 32, nbase = wn * 32;
        float acc[2][4][4];
#pragma unroll
        for (int i = 0; i < 2; i++)
#pragma unroll
            for (int j = 0; j < 4; j++)
#pragma unroll
                for (int c = 0; c < 4; c++) acc[i][j][c] = 0.f;

        int q = lane >> 3, riq = lane & 7;
#pragma unroll
        for (int ks = 0; ks < 8; ks++) {
            uint32_t ah[2][4], al[2][4], bh[4][2], bl[4][2];
#pragma unroll
            for (int i = 0; i < 2; i++) {
                int row = mbase + i * 16 + (q & 1) * 8 + riq;
                int kb = ks * 16 + (q >> 1) * 8;
                uint32_t addr = sb + SM_AH + row * (APAD * 2) + kb * 2;
                LDMATRIX_X4(ah[i], addr);
                LDMATRIX_X4(al[i], addr + AT_BYTES);
            }
#pragma unroll
            for (int j = 0; j < 2; j++) {
                int n = nbase + j * 16 + (q >> 1) * 8 + riq;
                int kb = ks * 16 + (q & 1) * 8;
                uint32_t addr = sb + SM_BH + n * (APAD * 2) + kb * 2;
                uint32_t t4[4];
                LDMATRIX_X4(t4, addr);
                bh[j * 2][0] = t4[0]; bh[j * 2][1] = t4[1];
                bh[j * 2 + 1][0] = t4[2]; bh[j * 2 + 1][1] = t4[3];
                LDMATRIX_X4(t4, addr + BT_BYTES);
                bl[j * 2][0] = t4[0]; bl[j * 2][1] = t4[1];
                bl[j * 2 + 1][0] = t4[2]; bl[j * 2 + 1][1] = t4[3];
            }
#pragma unroll
            for (int i = 0; i < 2; i++)
#pragma unroll
                for (int j = 0; j < 4; j++) {
                    MMA16816(acc[i][j], ah[i], bh[j]);
                    MMA16816(acc[i][j], ah[i], bl[j]);
                    MMA16816(acc[i][j], al[i], bh[j]);
                }
        }
        __syncthreads();   // A consumed; reuse A region for C staging (B preserved!)

        // ---- epilogue: regs -> smem (+bias, in A region) -> STG + fused stats ----
        float* sC = (float*)smem;   // 64 x 132 floats = 33792 B <= 34816 (Ah+Al)
        int g = lane >> 2, tc = (lane & 3) * 2;
#pragma unroll
        for (int i = 0; i < 2; i++) {
            int row0 = mbase + i * 16 + g;
#pragma unroll
            for (int j = 0; j < 4; j++) {
                int col = nbase + j * 8 + tc;
                float b0 = __ldg(&bias[col]), b1 = __ldg(&bias[col + 1]);
                sC[row0 * 132 + col]           = acc[i][j][0] + b0;
                sC[row0 * 132 + col + 1]       = acc[i][j][1] + b1;
                sC[(row0 + 8) * 132 + col]     = acc[i][j][2] + b0;
                sC[(row0 + 8) * 132 + col + 1] = acc[i][j][3] + b1;
            }
        }
        __syncthreads();

        {
            int r2 = tid >> 2, qt = tid & 3;
            if (m0 + r2 < M) {
                float4* dst = (float4*)(C + (size_t)(m0 + r2) * HID + qt * 32);
                const float4* src = (const float4*)(sC + r2 * 132 + qt * 32);
#pragma unroll
                for (int i = 0; i < 8; i++) dst[i] = src[i];
            }
        }

        {
            int nrows = min(64, M - m0);
            int c = tid & 127;
            int rbeg = (tid >> 7) * 32;
            int rend = min(rbeg + 32, nrows);
            float s = 0.f, s2 = 0.f;
            for (int rr = rbeg; rr < rend; rr++) {
                float v = sC[rr * 132 + c];
                s += v; s2 += v * v;
            }
            atomicAdd(&g_sum[oslot * HID + c], s);
            atomicAdd(&g_sumsq[oslot * HID + c], s2);
        }

        // ---- next tile (dynamic) ----
        if (tid == 0) s_tile = atomicAdd(&g_tile_ctr[widx], 1);
        __syncthreads();   // stats reads of sC done; s_tile visible
        t = s_tile;
    }
}

// ---------------- fused JK attention + pooling (warp-autonomous) ----------------
#define JKP_BLOCKS 500
#define JKP_WARPS (JKP_BLOCKS * 8)
__global__ void jk_pool_kernel(const int* __restrict__ batch, const float* __restrict__ att) {
    int wgid = blockIdx.x * 8 + (threadIdx.x >> 5);
    int lane = threadIdx.x & 31;
    const int CH = (N_NODES + JKP_WARPS - 1) / JKP_WARPS;   // 13
    int n0 = wgid * CH, n1 = min(n0 + CH, N_NODES);
    if (n0 >= n1) return;
    int c0 = lane * 4;

    float4 attc[NL];
#pragma unroll
    for (int l = 0; l < NL; l++)
        attc[l] = __ldg((const float4*)(att + l * HID) + lane);

    int g = __ldg(&batch[n0]);
    float4 s4 = make_float4(0.f, 0.f, 0.f, 0.f);
    float4 m4 = make_float4(-FLT_MAX, -FLT_MAX, -FLT_MAX, -FLT_MAX);
    int cnt = 0;

    for (int n = n0; n < n1; n++) {
        int gn = __ldg(&batch[n]);
        if (gn != g) {
            if (cnt > 0) {
                atomicAdd(&g_psum[g * HID + c0], s4.x);
                atomicAdd(&g_psum[g * HID + c0 + 1], s4.y);
                atomicAdd(&g_psum[g * HID + c0 + 2], s4.z);
                atomicAdd(&g_psum[g * HID + c0 + 3], s4.w);
                atomicMaxF(&g_pmax[g * HID + c0], m4.x);
                atomicMaxF(&g_pmax[g * HID + c0 + 1], m4.y);
                atomicMaxF(&g_pmax[g * HID + c0 + 2], m4.z);
                atomicMaxF(&g_pmax[g * HID + c0 + 3], m4.w);
                if (lane == 0) atomicAdd(&g_pcnt[g], cnt);
            }
            g = gn;
            s4 = make_float4(0.f, 0.f, 0.f, 0.f);
            m4 = make_float4(-FLT_MAX, -FLT_MAX, -FLT_MAX, -FLT_MAX);
            cnt = 0;
        }
        float4 v[NL];
        float p[NL];
#pragma unroll
        for (int l = 0; l < NL; l++) {
            v[l] = *(const float4*)(&g_hs[l][(size_t)n * HID + c0]);
            p[l] = v[l].x * attc[l].x + v[l].y * attc[l].y +
                   v[l].z * attc[l].z + v[l].w * attc[l].w;
        }
#pragma unroll
        for (int off = 16; off; off >>= 1) {
#pragma unroll
            for (int l = 0; l < NL; l++)
                p[l] += __shfl_xor_sync(0xffffffffu, p[l], off);
        }
        float m = fmaxf(fmaxf(p[0], p[1]), fmaxf(p[2], p[3]));
        float e[NL], tot = 0.f;
#pragma unroll
        for (int l = 0; l < NL; l++) {
            e[l] = expf((p[l] - m) * (1.0f / HID));
            tot += e[l];
        }
        float inv = 1.0f / tot;
        float4 xc = make_float4(0.f, 0.f, 0.f, 0.f);
#pragma unroll
        for (int l = 0; l < NL; l++) {
            float w = e[l] * inv;
            xc.x += w * v[l].x; xc.y += w * v[l].y;
            xc.z += w * v[l].z; xc.w += w * v[l].w;
        }
        s4.x += xc.x; s4.y += xc.y; s4.z += xc.z; s4.w += xc.w;
        m4.x = fmaxf(m4.x, xc.x); m4.y = fmaxf(m4.y, xc.y);
        m4.z = fmaxf(m4.z, xc.z); m4.w = fmaxf(m4.w, xc.w);
        cnt++;
    }
    if (cnt > 0) {
        atomicAdd(&g_psum[g * HID + c0], s4.x);
        atomicAdd(&g_psum[g * HID + c0 + 1], s4.y);
        atomicAdd(&g_psum[g * HID + c0 + 2], s4.z);
        atomicAdd(&g_psum[g * HID + c0 + 3], s4.w);
        atomicMaxF(&g_pmax[g * HID + c0], m4.x);
        atomicMaxF(&g_pmax[g * HID + c0 + 1], m4.y);
        atomicMaxF(&g_pmax[g * HID + c0 + 2], m4.z);
        atomicMaxF(&g_pmax[g * HID + c0 + 3], m4.w);
        if (lane == 0) atomicAdd(&g_pcnt[g], cnt);
    }
}

// ---------------- head ----------------
__global__ void head_kernel(const float* __restrict__ pwraw,
                            const float* __restrict__ fcA_w, const float* __restrict__ fcA_b,
                            const float* __restrict__ ln_g, const float* __restrict__ ln_b,
                            const float* __restrict__ fcB_w, const float* __restrict__ fcB_b,
                            float* __restrict__ out) {
    __shared__ float sp[HID];
    __shared__ float sh[HID];
    __shared__ float red[HID];
    int g = blockIdx.x, c = threadIdx.x;

    float w0 = pwraw[0], w1 = pwraw[1], w2 = pwraw[2];
    float mw = fmaxf(w0, fmaxf(w1, w2));
    float e0 = expf(w0 - mw), e1 = expf(w1 - mw), e2 = expf(w2 - mw);
    float et = 1.0f / (e0 + e1 + e2);
    float pw0 = e0 * et, pw1 = e1 * et, pw2 = e2 * et;

    float cnt = (float)g_pcnt[g];
    float s = g_psum[g * HID + c];
    float mean = s / fmaxf(cnt, 1.0f);
    float mx = (cnt > 0.f) ? g_pmax[g * HID + c] : 0.0f;
    float pooled = s * pw0 + mean * pw1 + mx * pw2;
    sp[c] = pooled;
    __syncthreads();

    float acc = fcA_b[c];
#pragma unroll 8
    for (int k = 0; k < HID; k++) acc += sp[k] * fcA_w[k * HID + c];

    red[c] = acc;
    __syncthreads();
    for (int st = 64; st > 0; st >>= 1) { if (c < st) red[c] += red[c + st]; __syncthreads(); }
    float mu = red[0] * (1.0f / HID);
    __syncthreads();
    float d = acc - mu;
    red[c] = d * d;
    __syncthreads();
    for (int st = 64; st > 0; st >>= 1) { if (c < st) red[c] += red[c + st]; __syncthreads(); }
    float var = red[0] * (1.0f / HID);
    float y = d * rsqrtf(var + 1e-5f) * ln_g[c] + ln_b[c];
    float h = gelu_exact(y) + pooled;
    sh[c] = h;
    __syncthreads();

    if (c < LAT) {
        float o = fcB_b[c];
#pragma unroll 8
        for (int k = 0; k < HID; k++) o += sh[k] * fcB_w[k * LAT + c];
        out[g * LAT + c] = o;
    }
}

// ---------------- launcher ----------------
extern "C" void kernel_launch(void* const* d_in, const int* in_sizes, int n_in,
                              void* d_out, int out_size) {
    const float* x      = (const float*)d_in[0];
    const int*   ei     = (const int*)d_in[1];
    const int*   batch  = (const int*)d_in[2];
    const float* ibn_g  = (const float*)d_in[3];
    const float* ibn_b  = (const float*)d_in[4];
    const float* eps    = (const float*)d_in[5];
    const float* fc1_w  = (const float*)d_in[6];
    const float* fc1_b  = (const float*)d_in[7];
    const float* bn1_g  = (const float*)d_in[8];
    const float* bn1_b  = (const float*)d_in[9];
    const float* fc2_w  = (const float*)d_in[10];
    const float* fc2_b  = (const float*)d_in[11];
    const float* bn_g   = (const float*)d_in[12];
    const float* bn_b   = (const float*)d_in[13];
    const float* att_w  = (const float*)d_in[14];
    const float* pool_w = (const float*)d_in[15];
    const float* fcA_w  = (const float*)d_in[16];
    const float* fcA_b  = (const float*)d_in[17];
    const float* ln_g   = (const float*)d_in[18];
    const float* ln_b   = (const float*)d_in[19];
    const float* fcB_w  = (const float*)d_in[20];
    const float* fcB_b  = (const float*)d_in[21];
    float* out = (float*)d_out;

    const int* srcp = ei;
    const int* dstp = ei + N_EDGES;

    cudaFuncSetAttribute(mma_gemm_kernel<0>, cudaFuncAttributeMaxDynamicSharedMemorySize, TC_SMEM);
    cudaFuncSetAttribute(mma_gemm_kernel<1>, cudaFuncAttributeMaxDynamicSharedMemorySize, TC_SMEM);

    float *p_h, *p_t, *p_hs;
    cudaGetSymbolAddress((void**)&p_h, g_h);
    cudaGetSymbolAddress((void**)&p_t, g_t);
    cudaGetSymbolAddress((void**)&p_hs, g_hs);

    const int EW_GRID   = (N_NODES * HID) / (256 * 4 * 2);  // 3125
    const int SCAN_GRID = (N_NODES + 1023) / 1024;          // 49

    prep_kernel<<<PREP_ZERO + PREP_WS + PREP_CS, 256>>>(x, fc1_w, fc2_w);
    hist_kernel<<<(N_EDGES + 511) / 512, 512>>>(dstp);
    scan1_kernel<<<SCAN_GRID, 1024>>>();
    scan3_kernel<<<SCAN_GRID, 1024>>>();
    scatter_kernel<<<(N_EDGES + 511) / 512, 512>>>(srcp, dstp);

    for (int l = 0; l < NL; l++) {
        int s1 = 1 + 2 * l, s2 = 2 + 2 * l;
        if (l == 0) {
            agg_kernel<1><<<N_NODES, 128>>>(x, 0, eps, ibn_g, ibn_b);
        } else {
            agg_kernel<0><<<N_NODES, 128>>>(p_hs + (size_t)(l - 1) * N_NODES * HID,
                                            l, eps, nullptr, nullptr);
        }
        mma_gemm_kernel<0><<<PGRID, 256, TC_SMEM>>>(p_h, l * 2 + 0, fc1_b + l * HID,
                                                    p_t, N_NODES, 0, nullptr, nullptr, s1);
        mma_gemm_kernel<1><<<PGRID, 256, TC_SMEM>>>(p_t, l * 2 + 1, fc2_b + l * HID,
                                                    p_t, N_NODES, s1,
                                                    bn1_g + l * HID, bn1_b + l * HID, s2);
        bn_apply_kernel<<<EW_GRID, 256>>>(p_t, p_hs + (size_t)l * N_NODES * HID,
                                          s2, bn_g + l * HID, bn_b + l * HID);
    }

    jk_pool_kernel<<<JKP_BLOCKS, 256>>>(batch, att_w);
    head_kernel<<<N_GRAPHS, 128>>>(pool_w, fcA_w, fcA_b, ln_g, ln_b, fcB_w, fcB_b, out);
}

// round 11
// speedup vs baseline: 1.4431x; 1.0276x over previous
#include <cuda_runtime.h>
#include <cuda_bf16.h>
#include <math.h>
#include <float.h>
#include <stdint.h>

#define N_NODES 50000
#define N_EDGES 600000
#define N_GRAPHS 512
#define HID 128
#define LAT 64
#define NL 4
#define NSLOT 10
#define NTILES 782          // ceil(N_NODES/64)
#define PGRID 296           // 2 CTAs x 148 SMs (persistent grid; all co-resident)

// ======================= scratch =======================
__device__ float g_h[N_NODES * HID];            // agg output / GEMM1 input
__device__ float g_t[N_NODES * HID];            // GEMM output buffer
__device__ float g_hs[NL][N_NODES * HID];       // per-layer hidden states (JK)
__device__ int   g_deg[N_NODES];
__device__ int   g_ptr[N_NODES + 1];
__device__ int   g_cursor[N_NODES];
__device__ int   g_srclist[N_EDGES];
__device__ int   g_bsum[64];
__device__ float g_sum[NSLOT * HID];
__device__ float g_sumsq[NSLOT * HID];
__device__ float g_psum[N_GRAPHS * HID];
__device__ float g_pmax[N_GRAPHS * HID];
__device__ int   g_pcnt[N_GRAPHS];
__device__ int   g_tilec[NL * 2];               // per-layer per-GEMM tile counters
__device__ int   g_syncc[NL * 3];               // per-layer grid-barrier counters
// per weight: 32KB hi + 32KB lo, B^T layout [n][k] row-major bf16
__device__ unsigned char g_wsplit[8][65536];

__device__ __forceinline__ float gelu_exact(float x) {
    return 0.5f * x * (1.0f + erff(x * 0.70710678118654752f));
}
__device__ __forceinline__ void atomicMaxF(float* addr, float v) {
    if (__float_as_int(v) >= 0) atomicMax((int*)addr, __float_as_int(v));
    else atomicMin((unsigned int*)addr, __float_as_uint(v));
}
__device__ __forceinline__ uint32_t smem_u32(const void* p) {
    uint32_t a;
    asm("{ .reg .u64 t; cvta.to.shared.u64 t, %1; cvt.u32.u64 %0, t; }" : "=r"(a) : "l"(p));
    return a;
}

#define LDMATRIX_X4(r, addr) \
    asm volatile("ldmatrix.sync.aligned.m8n8.x4.shared.b16 {%0,%1,%2,%3}, [%4];" \
        : "=r"((r)[0]), "=r"((r)[1]), "=r"((r)[2]), "=r"((r)[3]) : "r"(addr))

#define MMA16816(c, a, b) \
    asm volatile("mma.sync.aligned.m16n8k16.row.col.f32.bf16.bf16.f32 " \
        "{%0,%1,%2,%3}, {%4,%5,%6,%7}, {%8,%9}, {%0,%1,%2,%3};" \
        : "+f"((c)[0]), "+f"((c)[1]), "+f"((c)[2]), "+f"((c)[3]) \
        : "r"((a)[0]), "r"((a)[1]), "r"((a)[2]), "r"((a)[3]), "r"((b)[0]), "r"((b)[1]))

// BN finalize reading stats via L2 (__ldcg) — safe for same-kernel atomics
__device__ __forceinline__ void finalize_cg(int slot, const float* gamma,
                                            const float* beta,
                                            float* sScale, float* sShift, int tid) {
    if (tid < HID) {
        const float invN = 1.0f / N_NODES;
        float mean = __ldcg(&g_sum[slot * HID + tid]) * invN;
        float var  = __ldcg(&g_sumsq[slot * HID + tid]) * invN - mean * mean;
        float sc = __ldg(&gamma[tid]) * rsqrtf(var + 1e-5f);
        sScale[tid] = sc;
        sShift[tid] = __ldg(&beta[tid]) - mean * sc;
    }
}

// software grid barrier (all PGRID CTAs co-resident by construction)
__device__ __forceinline__ void grid_sync(int idx) {
    __syncthreads();
    if (threadIdx.x == 0) {
        __threadfence();
        atomicAdd(&g_syncc[idx], 1);
        while (atomicAdd(&g_syncc[idx], 0) < PGRID) __nanosleep(64);
        __threadfence();
    }
    __syncthreads();
}

// ======== merged prep: zero-init + weight split + input colstats ============
#define PREP_ZERO 256
#define PREP_WS 64
#define PREP_CS 256
__global__ void prep_kernel(const float* __restrict__ x,
                            const float* __restrict__ fc1_w,
                            const float* __restrict__ fc2_w) {
    int b = blockIdx.x, tid = threadIdx.x;
    if (b < PREP_ZERO) {
        int i = b * 256 + tid;
        if (i < NSLOT * HID) { g_sum[i] = 0.f; g_sumsq[i] = 0.f; }
        if (i < N_NODES) g_deg[i] = 0;
        if (i < N_GRAPHS * HID) { g_psum[i] = 0.f; g_pmax[i] = -FLT_MAX; }
        if (i < N_GRAPHS) g_pcnt[i] = 0;
        if (i < NL * 2) g_tilec[i] = PGRID;
        if (i < NL * 3) g_syncc[i] = 0;
    } else if (b < PREP_ZERO + PREP_WS) {
        int bb = b - PREP_ZERO;
        int w = bb >> 3;
        int l = w >> 1, which = w & 1;
        const float* W = (which ? fc2_w : fc1_w) + l * HID * HID;
        __nv_bfloat16* bh = (__nv_bfloat16*)(g_wsplit[w]);
        __nv_bfloat16* bl = (__nv_bfloat16*)(g_wsplit[w] + 32768);
        int chunk = bb & 7;
        for (int i = tid + chunk * 2048; i < (chunk + 1) * 2048; i += 256) {
            int n = i >> 7, k = i & 127;
            float v = W[k * HID + n];
            __nv_bfloat16 hi = __float2bfloat16_rn(v);
            bh[n * 128 + k] = hi;
            bl[n * 128 + k] = __float2bfloat16_rn(v - __bfloat162float(hi));
        }
    } else {
        int p = b - (PREP_ZERO + PREP_WS);
        int c = tid & 127;
        float s = 0.f, s2 = 0.f;
        for (int n = p * 2 + (tid >> 7); n < N_NODES; n += 512) {
            float v = x[n * HID + c];
            s += v; s2 += v * v;
        }
        atomicAdd(&g_sum[c], s);
        atomicAdd(&g_sumsq[c], s2);
    }
}

// ---------------- CSR build ----------------
__global__ void hist_kernel(const int* __restrict__ dst) {
    int i = blockIdx.x * blockDim.x + threadIdx.x;
    if (i < N_EDGES) atomicAdd(&g_deg[dst[i]], 1);
}

__global__ void scan1_kernel() {
    __shared__ int s[1024];
    int tid = threadIdx.x;
    int i = blockIdx.x * 1024 + tid;
    int v = (i < N_NODES) ? g_deg[i] : 0;
    s[tid] = v;
    __syncthreads();
#pragma unroll
    for (int d = 1; d < 1024; d <<= 1) {
        int t = (tid >= d) ? s[tid - d] : 0;
        __syncthreads();
        s[tid] += t;
        __syncthreads();
    }
    if (i < N_NODES) g_cursor[i] = s[tid];
    if (tid == 1023) g_bsum[blockIdx.x] = s[tid];
}

__global__ void scan3_kernel() {
    __shared__ int boff;
    if (threadIdx.x == 0) {
        int s = 0;
        for (int k = 0; k < blockIdx.x; k++) s += g_bsum[k];
        boff = s;
    }
    __syncthreads();
    int i = blockIdx.x * 1024 + threadIdx.x;
    if (i < N_NODES) {
        int p = boff + g_cursor[i] - g_deg[i];
        g_ptr[i] = p;
        g_cursor[i] = p;
    }
    if (i == 0) g_ptr[N_NODES] = N_EDGES;
}

__global__ void scatter_kernel(const int* __restrict__ src, const int* __restrict__ dst) {
    int i = blockIdx.x * blockDim.x + threadIdx.x;
    if (i < N_EDGES) {
        int pos = atomicAdd(&g_cursor[dst[i]], 1);
        g_srclist[pos] = src[i];
    }
}

// ---------------- persistent GEMM phase (device func, PRE = BN+GELU on A) ---
#define APAD 136
#define AT_BYTES (64 * APAD * 2)              // 17408
#define BT_BYTES (128 * APAD * 2)             // 34816
#define SM_AH 0
#define SM_AL AT_BYTES
#define SM_BH (2 * AT_BYTES)
#define SM_BL (2 * AT_BYTES + BT_BYTES)
#define SM_SC (2 * AT_BYTES + 2 * BT_BYTES)   // 104448
#define SM_SH (SM_SC + 512)
#define TC_SMEM (SM_SC + 1024)                // 105472 -> 2 CTAs/SM

template <int PRE>
__device__ __forceinline__ void gemm_phase(
    unsigned char* smem, uint32_t sb, int tid, int lane, int wid, int* s_tile_p,
    const float* __restrict__ A, int widx, const float* __restrict__ bias,
    float* __restrict__ C, int oslot, int* tile_ctr,
    const float* sScale, const float* sShift) {

    // ---- B: copy pre-split B^T (hi+lo) once per CTA ----
    {
        const uint4* srcH = (const uint4*)(g_wsplit[widx]);
        const uint4* srcL = (const uint4*)(g_wsplit[widx] + 32768);
#pragma unroll
        for (int it = 0; it < 8; it++) {
            int i = tid + it * 256;
            int n = i >> 4, s = i & 15;
            *(uint4*)(smem + SM_BH + n * (APAD * 2) + s * 16) = __ldg(srcH + i);
            *(uint4*)(smem + SM_BL + n * (APAD * 2) + s * 16) = __ldg(srcL + i);
        }
    }

    int t = blockIdx.x;
    while (t < NTILES) {
        int m0 = t * 64;
        __syncthreads();

        // ---- A: load (4 threads/row), optional BN+GELU, split hi/lo ----
        {
            int r = tid >> 2, qt = tid & 3;
            bool valid = (m0 + r) < N_NODES;
            const float4* Arow = (const float4*)(A + (size_t)(m0 + r) * HID + qt * 32);
#pragma unroll
            for (int jj = 0; jj < 8; jj++) {
                int col = qt * 32 + jj * 4;
                float4 v = valid ? __ldg(Arow + jj) : make_float4(0.f, 0.f, 0.f, 0.f);
                if (PRE) {
                    float4 sc = ((const float4*)sScale)[col >> 2];
                    float4 sh = ((const float4*)sShift)[col >> 2];
                    v.x = gelu_exact(v.x * sc.x + sh.x);
                    v.y = gelu_exact(v.y * sc.y + sh.y);
                    v.z = gelu_exact(v.z * sc.z + sh.z);
                    v.w = gelu_exact(v.w * sc.w + sh.w);
                }
                __nv_bfloat16 h0 = __float2bfloat16_rn(v.x), h1 = __float2bfloat16_rn(v.y);
                __nv_bfloat16 h2 = __float2bfloat16_rn(v.z), h3 = __float2bfloat16_rn(v.w);
                float l0 = v.x - __bfloat162float(h0), l1 = v.y - __bfloat162float(h1);
                float l2 = v.z - __bfloat162float(h2), l3 = v.w - __bfloat162float(h3);
                uint2 hp, lp;
                hp.x = (uint32_t)__bfloat16_as_ushort(h0) | ((uint32_t)__bfloat16_as_ushort(h1) << 16);
                hp.y = (uint32_t)__bfloat16_as_ushort(h2) | ((uint32_t)__bfloat16_as_ushort(h3) << 16);
                lp.x = (uint32_t)__bfloat16_as_ushort(__float2bfloat16_rn(l0)) |
                       ((uint32_t)__bfloat16_as_ushort(__float2bfloat16_rn(l1)) << 16);
                lp.y = (uint32_t)__bfloat16_as_ushort(__float2bfloat16_rn(l2)) |
                       ((uint32_t)__bfloat16_as_ushort(__float2bfloat16_rn(l3)) << 16);
                uint32_t off = r * (APAD * 2) + col * 2;
                *(uint2*)(smem + SM_AH + off) = hp;
                *(uint2*)(smem + SM_AL + off) = lp;
            }
        }
        __syncthreads();

        // ---- MMA mainloop: warp grid 2(M) x 4(N), warp tile 32x32 ----
        int wm = wid & 1, wn = wid >> 1;
        int mbase = wm * 32, nbase = wn * 32;
        float acc[2][4][4];
#pragma unroll
        for (int i = 0; i < 2; i++)
#pragma unroll
            for (int j = 0; j < 4; j++)
#pragma unroll
                for (int c = 0; c < 4; c++) acc[i][j][c] = 0.f;

        int q = lane >> 3, riq = lane & 7;
#pragma unroll
        for (int ks = 0; ks < 8; ks++) {
            uint32_t ah[2][4], al[2][4], bh[4][2], bl[4][2];
#pragma unroll
            for (int i = 0; i < 2; i++) {
                int row = mbase + i * 16 + (q & 1) * 8 + riq;
                int kb = ks * 16 + (q >> 1) * 8;
                uint32_t addr = sb + SM_AH + row * (APAD * 2) + kb * 2;
                LDMATRIX_X4(ah[i], addr);
                LDMATRIX_X4(al[i], addr + AT_BYTES);
            }
#pragma unroll
            for (int j = 0; j < 2; j++) {
                int n = nbase + j * 16 + (q >> 1) * 8 + riq;
                int kb = ks * 16 + (q & 1) * 8;
                uint32_t addr = sb + SM_BH + n * (APAD * 2) + kb * 2;
                uint32_t t4[4];
                LDMATRIX_X4(t4, addr);
                bh[j * 2][0] = t4[0]; bh[j * 2][1] = t4[1];
                bh[j * 2 + 1][0] = t4[2]; bh[j * 2 + 1][1] = t4[3];
                LDMATRIX_X4(t4, addr + BT_BYTES);
                bl[j * 2][0] = t4[0]; bl[j * 2][1] = t4[1];
                bl[j * 2 + 1][0] = t4[2]; bl[j * 2 + 1][1] = t4[3];
            }
#pragma unroll
            for (int i = 0; i < 2; i++)
#pragma unroll
                for (int j = 0; j < 4; j++) {
                    MMA16816(acc[i][j], ah[i], bh[j]);
                    MMA16816(acc[i][j], ah[i], bl[j]);
                    MMA16816(acc[i][j], al[i], bh[j]);
                }
        }
        __syncthreads();   // A consumed; reuse A region for C staging

        float* sC = (float*)smem;
        int g = lane >> 2, tc = (lane & 3) * 2;
#pragma unroll
        for (int i = 0; i < 2; i++) {
            int row0 = mbase + i * 16 + g;
#pragma unroll
            for (int j = 0; j < 4; j++) {
                int col = nbase + j * 8 + tc;
                float b0 = __ldg(&bias[col]), b1 = __ldg(&bias[col + 1]);
                sC[row0 * 132 + col]           = acc[i][j][0] + b0;
                sC[row0 * 132 + col + 1]       = acc[i][j][1] + b1;
                sC[(row0 + 8) * 132 + col]     = acc[i][j][2] + b0;
                sC[(row0 + 8) * 132 + col + 1] = acc[i][j][3] + b1;
            }
        }
        __syncthreads();

        {
            int r2 = tid >> 2, qt = tid & 3;
            if (m0 + r2 < N_NODES) {
                float4* dst = (float4*)(C + (size_t)(m0 + r2) * HID + qt * 32);
                const float4* src = (const float4*)(sC + r2 * 132 + qt * 32);
#pragma unroll
                for (int i = 0; i < 8; i++) dst[i] = src[i];
            }
        }

        {
            int nrows = min(64, N_NODES - m0);
            int c = tid & 127;
            int rbeg = (tid >> 7) * 32;
            int rend = min(rbeg + 32, nrows);
            float s = 0.f, s2 = 0.f;
            for (int rr = rbeg; rr < rend; rr++) {
                float v = sC[rr * 132 + c];
                s += v; s2 += v * v;
            }
            atomicAdd(&g_sum[oslot * HID + c], s);
            atomicAdd(&g_sumsq[oslot * HID + c], s2);
        }

        if (tid == 0) *s_tile_p = atomicAdd(tile_ctr, 1);
        __syncthreads();
        t = *s_tile_p;
    }
}

// ---------------- whole layer: agg -> GEMM1 -> GEMM2 -> BN (one launch) -----
template <int L0>
__global__ void __launch_bounds__(256, 2)
layer_kernel(const float* __restrict__ Ain, int layer,
             const float* __restrict__ eps,
             const float* __restrict__ ibn_g, const float* __restrict__ ibn_b,
             const float* __restrict__ fc1_b,
             const float* __restrict__ bn1_g, const float* __restrict__ bn1_b,
             const float* __restrict__ fc2_b,
             const float* __restrict__ bn_g, const float* __restrict__ bn_b,
             float* __restrict__ hs_out) {
    extern __shared__ unsigned char smem[];
    __shared__ int s_tile;
    int tid = threadIdx.x, lane = tid & 31, wid = tid >> 5;
    uint32_t sb = smem_u32(smem);
    float* sScale = (float*)(smem + SM_SC);
    float* sShift = (float*)(smem + SM_SH);
    int s1 = 1 + 2 * layer, s2 = 2 + 2 * layer;

    // ===== phase 0: GIN aggregation (warp per node, float4 lanes) =====
    if (L0) {
        finalize_cg(0, ibn_g, ibn_b, sScale, sShift, tid);
        __syncthreads();
    }
    {
        float ev = __ldg(&eps[layer]);
        float op = 1.0f + ev;
        float4 sc4, sh4;
        if (L0) { sc4 = ((const float4*)sScale)[lane]; sh4 = ((const float4*)sShift)[lane]; }
        for (int n = blockIdx.x * 8 + wid; n < N_NODES; n += PGRID * 8) {
            float4 a = __ldg((const float4*)(Ain + (size_t)n * HID) + lane);
            float4 acc = make_float4(op * a.x, op * a.y, op * a.z, op * a.w);
            int b = g_ptr[n], e = g_ptr[n + 1];
            int j = b;
            for (; j + 1 < e; j += 2) {
                int q0 = g_srclist[j], q1 = g_srclist[j + 1];
                float4 v0 = __ldg((const float4*)(Ain + (size_t)q0 * HID) + lane);
                float4 v1 = __ldg((const float4*)(Ain + (size_t)q1 * HID) + lane);
                acc.x += v0.x + v1.x; acc.y += v0.y + v1.y;
                acc.z += v0.z + v1.z; acc.w += v0.w + v1.w;
            }
            if (j < e) {
                float4 v0 = __ldg((const float4*)(Ain + (size_t)g_srclist[j] * HID) + lane);
                acc.x += v0.x; acc.y += v0.y; acc.z += v0.z; acc.w += v0.w;
            }
            if (L0) {
                float shf = op + (float)(e - b);
                acc.x = sc4.x * acc.x + shf * sh4.x;
                acc.y = sc4.y * acc.y + shf * sh4.y;
                acc.z = sc4.z * acc.z + shf * sh4.z;
                acc.w = sc4.w * acc.w + shf * sh4.w;
            }
            *((float4*)(g_h + (size_t)n * HID) + lane) = acc;
        }
    }
    grid_sync(layer * 3 + 0);

    // ===== phase 1: GEMM1 (A = g_h, W = fc1, stats -> s1) =====
    gemm_phase<0>(smem, sb, tid, lane, wid, &s_tile,
                  g_h, layer * 2, fc1_b, g_t, s1, &g_tilec[layer * 2],
                  sScale, sShift);
    grid_sync(layer * 3 + 1);

    // ===== phase 2: GEMM2 (A = BN(s1)+GELU(g_t), W = fc2, stats -> s2) =====
    finalize_cg(s1, bn1_g, bn1_b, sScale, sShift, tid);
    gemm_phase<1>(smem, sb, tid, lane, wid, &s_tile,
                  g_t, layer * 2 + 1, fc2_b, g_t, s2, &g_tilec[layer * 2 + 1],
                  sScale, sShift);
    grid_sync(layer * 3 + 2);

    // ===== phase 3: BN(s2)+GELU elementwise g_t -> hs_out =====
    finalize_cg(s2, bn_g, bn_b, sScale, sShift, tid);
    __syncthreads();
    const int total = N_NODES * HID / 4;
    for (int idx = blockIdx.x * 256 + tid; idx < total; idx += PGRID * 256) {
        int c4 = idx & 31;
        // __ldcg: bypass L1 (g_t lines may be stale in L1 from phase-2 __ldg)
        float4 v;
        v.x = __ldcg(g_t + idx * 4);
        v.y = __ldcg(g_t + idx * 4 + 1);
        v.z = __ldcg(g_t + idx * 4 + 2);
        v.w = __ldcg(g_t + idx * 4 + 3);
        float4 sc = ((const float4*)sScale)[c4];
        float4 sh = ((const float4*)sShift)[c4];
        v.x = gelu_exact(v.x * sc.x + sh.x);
        v.y = gelu_exact(v.y * sc.y + sh.y);
        v.z = gelu_exact(v.z * sc.z + sh.z);
        v.w = gelu_exact(v.w * sc.w + sh.w);
        ((float4*)hs_out)[idx] = v;
    }
}

// ---------------- fused JK attention + pooling (warp-autonomous) ----------------
#define JKP_BLOCKS 500
#define JKP_WARPS (JKP_BLOCKS * 8)
__global__ void jk_pool_kernel(const int* __restrict__ batch, const float* __restrict__ att) {
    int wgid = blockIdx.x * 8 + (threadIdx.x >> 5);
    int lane = threadIdx.x & 31;
    const int CH = (N_NODES + JKP_WARPS - 1) / JKP_WARPS;   // 13
    int n0 = wgid * CH, n1 = min(n0 + CH, N_NODES);
    if (n0 >= n1) return;
    int c0 = lane * 4;

    float4 attc[NL];
#pragma unroll
    for (int l = 0; l < NL; l++)
        attc[l] = __ldg((const float4*)(att + l * HID) + lane);

    int g = __ldg(&batch[n0]);
    float4 s4 = make_float4(0.f, 0.f, 0.f, 0.f);
    float4 m4 = make_float4(-FLT_MAX, -FLT_MAX, -FLT_MAX, -FLT_MAX);
    int cnt = 0;

    for (int n = n0; n < n1; n++) {
        int gn = __ldg(&batch[n]);
        if (gn != g) {
            if (cnt > 0) {
                atomicAdd(&g_psum[g * HID + c0], s4.x);
                atomicAdd(&g_psum[g * HID + c0 + 1], s4.y);
                atomicAdd(&g_psum[g * HID + c0 + 2], s4.z);
                atomicAdd(&g_psum[g * HID + c0 + 3], s4.w);
                atomicMaxF(&g_pmax[g * HID + c0], m4.x);
                atomicMaxF(&g_pmax[g * HID + c0 + 1], m4.y);
                atomicMaxF(&g_pmax[g * HID + c0 + 2], m4.z);
                atomicMaxF(&g_pmax[g * HID + c0 + 3], m4.w);
                if (lane == 0) atomicAdd(&g_pcnt[g], cnt);
            }
            g = gn;
            s4 = make_float4(0.f, 0.f, 0.f, 0.f);
            m4 = make_float4(-FLT_MAX, -FLT_MAX, -FLT_MAX, -FLT_MAX);
            cnt = 0;
        }
        float4 v[NL];
        float p[NL];
#pragma unroll
        for (int l = 0; l < NL; l++) {
            v[l] = *(const float4*)(&g_hs[l][(size_t)n * HID + c0]);
            p[l] = v[l].x * attc[l].x + v[l].y * attc[l].y +
                   v[l].z * attc[l].z + v[l].w * attc[l].w;
        }
#pragma unroll
        for (int off = 16; off; off >>= 1) {
#pragma unroll
            for (int l = 0; l < NL; l++)
                p[l] += __shfl_xor_sync(0xffffffffu, p[l], off);
        }
        float m = fmaxf(fmaxf(p[0], p[1]), fmaxf(p[2], p[3]));
        float e[NL], tot = 0.f;
#pragma unroll
        for (int l = 0; l < NL; l++) {
            e[l] = expf((p[l] - m) * (1.0f / HID));
            tot += e[l];
        }
        float inv = 1.0f / tot;
        float4 xc = make_float4(0.f, 0.f, 0.f, 0.f);
#pragma unroll
        for (int l = 0; l < NL; l++) {
            float w = e[l] * inv;
            xc.x += w * v[l].x; xc.y += w * v[l].y;
            xc.z += w * v[l].z; xc.w += w * v[l].w;
        }
        s4.x += xc.x; s4.y += xc.y; s4.z += xc.z; s4.w += xc.w;
        m4.x = fmaxf(m4.x, xc.x); m4.y = fmaxf(m4.y, xc.y);
        m4.z = fmaxf(m4.z, xc.z); m4.w = fmaxf(m4.w, xc.w);
        cnt++;
    }
    if (cnt > 0) {
        atomicAdd(&g_psum[g * HID + c0], s4.x);
        atomicAdd(&g_psum[g * HID + c0 + 1], s4.y);
        atomicAdd(&g_psum[g * HID + c0 + 2], s4.z);
        atomicAdd(&g_psum[g * HID + c0 + 3], s4.w);
        atomicMaxF(&g_pmax[g * HID + c0], m4.x);
        atomicMaxF(&g_pmax[g * HID + c0 + 1], m4.y);
        atomicMaxF(&g_pmax[g * HID + c0 + 2], m4.z);
        atomicMaxF(&g_pmax[g * HID + c0 + 3], m4.w);
        if (lane == 0) atomicAdd(&g_pcnt[g], cnt);
    }
}

// ---------------- head ----------------
__global__ void head_kernel(const float* __restrict__ pwraw,
                            const float* __restrict__ fcA_w, const float* __restrict__ fcA_b,
                            const float* __restrict__ ln_g, const float* __restrict__ ln_b,
                            const float* __restrict__ fcB_w, const float* __restrict__ fcB_b,
                            float* __restrict__ out) {
    __shared__ float sp[HID];
    __shared__ float sh[HID];
    __shared__ float red[HID];
    int g = blockIdx.x, c = threadIdx.x;

    float w0 = pwraw[0], w1 = pwraw[1], w2 = pwraw[2];
    float mw = fmaxf(w0, fmaxf(w1, w2));
    float e0 = expf(w0 - mw), e1 = expf(w1 - mw), e2 = expf(w2 - mw);
    float et = 1.0f / (e0 + e1 + e2);
    float pw0 = e0 * et, pw1 = e1 * et, pw2 = e2 * et;

    float cnt = (float)g_pcnt[g];
    float s = g_psum[g * HID + c];
    float mean = s / fmaxf(cnt, 1.0f);
    float mx = (cnt > 0.f) ? g_pmax[g * HID + c] : 0.0f;
    float pooled = s * pw0 + mean * pw1 + mx * pw2;
    sp[c] = pooled;
    __syncthreads();

    float acc = fcA_b[c];
#pragma unroll 8
    for (int k = 0; k < HID; k++) acc += sp[k] * fcA_w[k * HID + c];

    red[c] = acc;
    __syncthreads();
    for (int st = 64; st > 0; st >>= 1) { if (c < st) red[c] += red[c + st]; __syncthreads(); }
    float mu = red[0] * (1.0f / HID);
    __syncthreads();
    float d = acc - mu;
    red[c] = d * d;
    __syncthreads();
    for (int st = 64; st > 0; st >>= 1) { if (c < st) red[c] += red[c + st]; __syncthreads(); }
    float var = red[0] * (1.0f / HID);
    float y = d * rsqrtf(var + 1e-5f) * ln_g[c] + ln_b[c];
    float h = gelu_exact(y) + pooled;
    sh[c] = h;
    __syncthreads();

    if (c < LAT) {
        float o = fcB_b[c];
#pragma unroll 8
        for (int k = 0; k < HID; k++) o += sh[k] * fcB_w[k * LAT + c];
        out[g * LAT + c] = o;
    }
}

// ---------------- launcher ----------------
extern "C" void kernel_launch(void* const* d_in, const int* in_sizes, int n_in,
                              void* d_out, int out_size) {
    const float* x      = (const float*)d_in[0];
    const int*   ei     = (const int*)d_in[1];
    const int*   batch  = (const int*)d_in[2];
    const float* ibn_g  = (const float*)d_in[3];
    const float* ibn_b  = (const float*)d_in[4];
    const float* eps    = (const float*)d_in[5];
    const float* fc1_w  = (const float*)d_in[6];
    const float* fc1_b  = (const float*)d_in[7];
    const float* bn1_g  = (const float*)d_in[8];
    const float* bn1_b  = (const float*)d_in[9];
    const float* fc2_w  = (const float*)d_in[10];
    const float* fc2_b  = (const float*)d_in[11];
    const float* bn_g   = (const float*)d_in[12];
    const float* bn_b   = (const float*)d_in[13];
    const float* att_w  = (const float*)d_in[14];
    const float* pool_w = (const float*)d_in[15];
    const float* fcA_w  = (const float*)d_in[16];
    const float* fcA_b  = (const float*)d_in[17];
    const float* ln_g   = (const float*)d_in[18];
    const float* ln_b   = (const float*)d_in[19];
    const float* fcB_w  = (const float*)d_in[20];
    const float* fcB_b  = (const float*)d_in[21];
    float* out = (float*)d_out;

    const int* srcp = ei;
    const int* dstp = ei + N_EDGES;

    cudaFuncSetAttribute(layer_kernel<0>, cudaFuncAttributeMaxDynamicSharedMemorySize, TC_SMEM);
    cudaFuncSetAttribute(layer_kernel<1>, cudaFuncAttributeMaxDynamicSharedMemorySize, TC_SMEM);

    float* p_hs;
    cudaGetSymbolAddress((void**)&p_hs, g_hs);

    const int SCAN_GRID = (N_NODES + 1023) / 1024;          // 49

    prep_kernel<<<PREP_ZERO + PREP_WS + PREP_CS, 256>>>(x, fc1_w, fc2_w);
    hist_kernel<<<(N_EDGES + 511) / 512, 512>>>(dstp);
    scan1_kernel<<<SCAN_GRID, 1024>>>();
    scan3_kernel<<<SCAN_GRID, 1024>>>();
    scatter_kernel<<<(N_EDGES + 511) / 512, 512>>>(srcp, dstp);

    layer_kernel<1><<<PGRID, 256, TC_SMEM>>>(
        x, 0, eps, ibn_g, ibn_b,
        fc1_b, bn1_g, bn1_b, fc2_b, bn_g, bn_b,
        p_hs);
    for (int l = 1; l < NL; l++) {
        layer_kernel<0><<<PGRID, 256, TC_SMEM>>>(
            p_hs + (size_t)(l - 1) * N_NODES * HID, l, eps, nullptr, nullptr,
            fc1_b + l * HID, bn1_g + l * HID, bn1_b + l * HID,
            fc2_b + l * HID, bn_g + l * HID, bn_b + l * HID,
            p_hs + (size_t)l * N_NODES * HID);
    }

    jk_pool_kernel<<<JKP_BLOCKS, 256>>>(batch, att_w);
    head_kernel<<<N_GRAPHS, 128>>>(pool_w, fcA_w, fcA_b, ln_g, ln_b, fcB_w, fcB_b, out);
}